// round 10
// baseline (speedup 1.0000x reference)
#include <cuda_runtime.h>
#include <cstdint>

#define NNODES 50000
#define NEDGES 600000
#define HID 128
#define OUTC 64
#define NGCN 4
#define EPSBN 1e-5f
#define SKIPW 0.5f

#define SCAN_CHUNK 200
#define SCAN_NBLK 250  // 250*200 = 50000

#define WTF_TOTAL (HID * HID * 5 + HID * OUTC)

// ---------------- scratch (static device globals; no runtime alloc) ----------------
__device__ float g_t[NNODES * HID];
__device__ float g_agg[NNODES * HID];
__device__ float g_h0[NNODES * HID];  // input-linear output == skip
__device__ float g_acc[NNODES * HID];
__device__ float g_dis[NNODES];
__device__ float g_stats[NGCN * 2 * HID];
__device__ __align__(16) uint32_t g_wtf[WTF_TOTAL];  // weights, tf32, FRAGMENT-PACKED
__device__ int g_cnt[NNODES];
__device__ int g_rowptr[NNODES + 1];
__device__ int g_col[NEDGES];
__device__ float g_w[NEDGES];
__device__ int g_blockoff[SCAN_NBLK];
__device__ int g_is64;

// ---------------- edge-index dtype detection ----------------
__global__ void detect_kernel(const long long* __restrict__ ei64) {
    __shared__ int ok;
    if (threadIdx.x == 0) ok = 1;
    __syncthreads();
    for (int i = threadIdx.x; i < 4096; i += blockDim.x) {
        long long v = ei64[i];
        if (v < 0 || v >= NNODES) ok = 0;
    }
    __syncthreads();
    if (threadIdx.x == 0) g_is64 = ok;
}

__device__ __forceinline__ int load_idx(const void* ei, int pos, int is64) {
    if (is64) return (int)((const long long*)ei)[pos];
    return ((const int*)ei)[pos];
}

__device__ __forceinline__ uint32_t f2tf(float f) {
    uint32_t u;
    asm("cvt.rna.tf32.f32 %0, %1;" : "=r"(u) : "f"(f));
    return u;
}

// ---------------- pack all weights to tf32 in mma-fragment order ----------------
// For each (ks8, nb, lane): word0 = W[ks8*8 + (lane&3)][nb*8 + (lane>>2)]
//                           word1 = W[ks8*8 + (lane&3) + 4][nb*8 + (lane>>2)]
// Layout index: ((ks8*(BN/8) + nb)*32 + lane)*2 + {0,1}
__device__ __forceinline__ void wpack_one(const float* __restrict__ src,
                                          uint32_t* __restrict__ dst, int BN, int r) {
    int lane = r & 31;
    int blk = r >> 5;
    int nb = blk % (BN / 8);
    int ks8 = blk / (BN / 8);
    int k0 = ks8 * 8 + (lane & 3);
    int n = nb * 8 + (lane >> 2);
    dst[r * 2 + 0] = f2tf(src[(size_t)k0 * BN + n]);
    dst[r * 2 + 1] = f2tf(src[(size_t)(k0 + 4) * BN + n]);
}

__global__ void wpack_kernel(const float* __restrict__ W_in, const float* __restrict__ W_g,
                             const float* __restrict__ W_out, uint32_t* __restrict__ wtf) {
    int idx = blockIdx.x * blockDim.x + threadIdx.x;
    if (idx < 5 * 8192) {
        int m = idx / 8192;
        int r = idx % 8192;
        const float* src = (m == 0) ? W_in : (W_g + (size_t)(m - 1) * HID * HID);
        wpack_one(src, wtf + (size_t)m * 16384, 128, r);
    } else if (idx < 5 * 8192 + 4096) {
        int r = idx - 5 * 8192;
        wpack_one(W_out, wtf + (size_t)5 * 16384, 64, r);
    }
}

// ---------------- CSR build ----------------
__global__ void zero_all_kernel(int* cnt, float* stats) {
    int i = blockIdx.x * blockDim.x + threadIdx.x;
    if (i < NNODES) cnt[i] = 0;
    if (i < NGCN * 2 * HID) stats[i] = 0.0f;
}

__global__ void count_kernel(const void* __restrict__ ei, int* cnt, int E) {
    int e = blockIdx.x * blockDim.x + threadIdx.x;
    if (e < E) atomicAdd(&cnt[load_idx(ei, E + e, g_is64)], 1);
}

// inclusive scan within chunk; also compute dis from cnt
__global__ void scan1_kernel(const int* __restrict__ cnt, int* rowptr, int* blockoff,
                             float* dis) {
    __shared__ int s[256];
    int b = blockIdx.x, t = threadIdx.x;
    int i = b * SCAN_CHUNK + t;
    int v = (t < SCAN_CHUNK) ? cnt[i] : 0;
    if (t < SCAN_CHUNK) dis[i] = rsqrtf((float)v + 1.0f);  // self-loop degree
    s[t] = v;
    __syncthreads();
#pragma unroll
    for (int d = 1; d < 256; d <<= 1) {
        int add = (t >= d) ? s[t - d] : 0;
        __syncthreads();
        s[t] += add;
        __syncthreads();
    }
    if (t < SCAN_CHUNK) rowptr[i + 1] = s[t];
    if (t == 255) blockoff[b] = s[SCAN_CHUNK - 1];
}

__global__ void scan2_kernel(int* blockoff) {
    __shared__ int s[256];
    int t = threadIdx.x;
    int v = (t < SCAN_NBLK) ? blockoff[t] : 0;
    s[t] = v;
    __syncthreads();
#pragma unroll
    for (int d = 1; d < 256; d <<= 1) {
        int add = (t >= d) ? s[t - d] : 0;
        __syncthreads();
        s[t] += add;
        __syncthreads();
    }
    if (t < SCAN_NBLK) blockoff[t] = s[t] - v;  // exclusive
}

__global__ void scan3_kernel(int* rowptr, const int* __restrict__ blockoff) {
    int b = blockIdx.x, t = threadIdx.x;
    int i = b * SCAN_CHUNK + t;
    if (t < SCAN_CHUNK) rowptr[i + 1] += blockoff[b];
    if (b == 0 && t == 0) rowptr[0] = 0;
}

__global__ void scatter_kernel(const void* __restrict__ ei, const float* __restrict__ dis,
                               const int* __restrict__ rowptr, int* cnt,
                               int* col, float* w, int E) {
    int e = blockIdx.x * blockDim.x + threadIdx.x;
    if (e >= E) return;
    int is64 = g_is64;
    int src = load_idx(ei, e, is64);
    int dst = load_idx(ei, E + e, is64);
    int p = rowptr[dst] + atomicAdd(&cnt[dst], 1);
    col[p] = src;
    w[p] = dis[src] * dis[dst];
}

// ---------------- TF32 tensor-core GEMM, DIRECT-LDG fragment A path ----------------
// C[M,BN] = f(A)[M,128] @ Wtf[128,BN]; block covers 128 rows x 64 cols (grid.y = BN/64)
// AMODE 0: A plain
// AMODE 1: A = relu(agg*sc+sh);            acc  = A (scalar STG)
// AMODE 2: A = relu(agg*sc+sh + 0.5*skip); acc += A (scalar RED)
// AMODE 3: A = relu(agg*sc+sh);            acc += A (scalar RED)
// AMODE 4: A = accOld + relu(agg*sc+sh + 0.5*skip)   (output GEMM; no side effect)
// EPI 1: C += bias
#define MMA_TF32(d, a0, a1, a2, a3, b0, b1)                                    \
    asm volatile(                                                              \
        "mma.sync.aligned.m16n8k8.row.col.f32.tf32.tf32.f32 "                  \
        "{%0,%1,%2,%3}, {%4,%5,%6,%7}, {%8,%9}, {%0,%1,%2,%3};"                \
        : "+f"((d)[0]), "+f"((d)[1]), "+f"((d)[2]), "+f"((d)[3])               \
        : "r"(a0), "r"(a1), "r"(a2), "r"(a3), "r"(b0), "r"(b1))

template <int BN, int AMODE, int EPI>
__global__ __launch_bounds__(256, 3) void gemm_tc(
    const float* __restrict__ Ain, const uint32_t* __restrict__ Wtf,
    const float* __restrict__ bias, const float* __restrict__ stats,
    const float* __restrict__ gamma, const float* __restrict__ beta,
    const float* __restrict__ skipb, float* __restrict__ accb,
    float* __restrict__ C, int M) {
    constexpr int NB8TOT = BN / 8;
    constexpr bool HASSKIP = (AMODE == 2 || AMODE == 4);

    __shared__ __align__(16) uint32_t Bs[16 * 8 * 64];  // [ksg][nbl][lane][2] = 32KB
    __shared__ float sscale[HID];
    __shared__ float sshift[HID];

    const int tid = threadIdx.x;
    const int lane = tid & 31;
    const int wid = tid >> 5;
    const int row0 = blockIdx.x * 128;
    const int by = blockIdx.y;
    const int wm = (wid & 3) * 32;           // warp row offset
    const int wng = wid >> 2;                // n-warp-group (0/1)
    const bool sider =
        (AMODE == 1 || AMODE == 2 || AMODE == 3) && (by == 0) && (wng == 0);

    if (AMODE != 0 && tid < HID) {
        float invN = 1.0f / (float)M;
        float mean = stats[tid] * invN;
        float var = stats[HID + tid] * invN - mean * mean;
        float sc = gamma[tid] * rsqrtf(var + EPSBN);
        sscale[tid] = sc;
        sshift[tid] = beta[tid] - mean * sc;
    }
    // stage this block's 64-col W panel (pure uint4 copies)
    {
        const uint4* src = (const uint4*)Wtf;
        uint4* dst = (uint4*)Bs;
        for (int i = tid; i < 2048; i += 256) {
            int run = i >> 4;  // ksg*8 + nbl
            int off = i & 15;
            int ksg = run >> 3, nbl = run & 7;
            dst[i] = src[(ksg * NB8TOT + by * 8 + nbl) * 16 + off];
        }
    }
    __syncthreads();  // the ONLY barrier

    float fa[2][4][4];
#pragma unroll
    for (int mi = 0; mi < 2; mi++)
#pragma unroll
        for (int ni = 0; ni < 4; ni++)
#pragma unroll
            for (int j = 0; j < 4; j++) fa[mi][ni][j] = 0.0f;

    const int lg = lane >> 2;
    const int q = lane & 3;
    const int r_base = row0 + wm + lg;

    // per-element fragment load with fused transform / side-effects
    auto elem = [&](int r, int c, float sc, float sh) -> uint32_t {
        float v = (r < M) ? __ldg(Ain + (size_t)r * HID + c) : 0.0f;
        if (AMODE != 0) {
            v = v * sc + sh;
            if (HASSKIP) {
                float s = (r < M) ? __ldg(skipb + (size_t)r * HID + c) : 0.0f;
                v += SKIPW * s;
            }
            v = fmaxf(v, 0.0f);
            if (sider && r < M) {
                if (AMODE == 1)
                    accb[(size_t)r * HID + c] = v;
                else
                    asm volatile("red.global.add.f32 [%0], %1;" ::
                                     "l"(accb + (size_t)r * HID + c), "f"(v)
                                 : "memory");
            }
            if (AMODE == 4) {
                float a0 = (r < M) ? __ldg(accb + (size_t)r * HID + c) : 0.0f;
                v += a0;
            }
        }
        return f2tf(v);
    };

#pragma unroll 4
    for (int ksg = 0; ksg < 16; ksg++) {
        const int c0 = ksg * 8 + q;
        float sc0 = 0.f, sh0 = 0.f, sc1 = 0.f, sh1 = 0.f;
        if (AMODE != 0) {
            sc0 = sscale[c0];
            sh0 = sshift[c0];
            sc1 = sscale[c0 + 4];
            sh1 = sshift[c0 + 4];
        }
        uint32_t afr[2][4];
#pragma unroll
        for (int mi = 0; mi < 2; mi++) {
            int r0 = r_base + mi * 16;
            int r1 = r0 + 8;
            afr[mi][0] = elem(r0, c0, sc0, sh0);
            afr[mi][1] = elem(r1, c0, sc0, sh0);
            afr[mi][2] = elem(r0, c0 + 4, sc1, sh1);
            afr[mi][3] = elem(r1, c0 + 4, sc1, sh1);
        }
        uint2 bf[4];
#pragma unroll
        for (int ni = 0; ni < 4; ni++)
            bf[ni] = *(const uint2*)&Bs[((ksg * 8 + wng * 4 + ni) * 32 + lane) * 2];
#pragma unroll
        for (int ni = 0; ni < 4; ni++) {
            MMA_TF32(fa[0][ni], afr[0][0], afr[0][1], afr[0][2], afr[0][3], bf[ni].x, bf[ni].y);
            MMA_TF32(fa[1][ni], afr[1][0], afr[1][1], afr[1][2], afr[1][3], bf[ni].x, bf[ni].y);
        }
    }

    // epilogue
#pragma unroll
    for (int mi = 0; mi < 2; mi++) {
        int rb = row0 + wm + mi * 16 + lg;
#pragma unroll
        for (int half = 0; half < 2; half++) {
            int r = rb + half * 8;
            if (r >= M) continue;
#pragma unroll
            for (int ni = 0; ni < 4; ni++) {
                int c = by * 64 + wng * 32 + ni * 8 + q * 2;
                float v0 = fa[mi][ni][half * 2 + 0];
                float v1 = fa[mi][ni][half * 2 + 1];
                if (EPI) {
                    v0 += bias[c];
                    v1 += bias[c + 1];
                }
                *(float2*)(C + (size_t)r * BN + c) = make_float2(v0, v1);
            }
        }
    }
}

// ---------------- CSR aggregation + fused BN stats ----------------
__global__ __launch_bounds__(256) void agg_stats_kernel(
    const float* __restrict__ t, const float* __restrict__ dis,
    const int* __restrict__ rowptr, const int* __restrict__ col,
    const float* __restrict__ w, const float* __restrict__ bias,
    float* __restrict__ agg, float* __restrict__ stats) {
    __shared__ float ssum[HID];
    __shared__ float ssq[HID];
    const int tid = threadIdx.x;
    const int lane = tid & 31;
    const int widx = tid >> 5;
    if (tid < HID) {
        ssum[tid] = 0.0f;
        ssq[tid] = 0.0f;
    }
    __syncthreads();

    const int row = blockIdx.x * 8 + widx;  // grid = NNODES/8
    const float4* t4 = (const float4*)t;

    float d = dis[row];
    float sn = d * d;
    float4 a = __ldg(t4 + (size_t)row * 32 + lane);
    a.x *= sn; a.y *= sn; a.z *= sn; a.w *= sn;

    const int e0 = rowptr[row];
    const int e1 = rowptr[row + 1];
    int e = e0;
    for (; e + 4 <= e1; e += 4) {
        int s0 = __ldg(col + e + 0), s1 = __ldg(col + e + 1);
        int s2 = __ldg(col + e + 2), s3 = __ldg(col + e + 3);
        float w0 = __ldg(w + e + 0), w1 = __ldg(w + e + 1);
        float w2 = __ldg(w + e + 2), w3 = __ldg(w + e + 3);
        float4 v0 = __ldg(t4 + (size_t)s0 * 32 + lane);
        float4 v1 = __ldg(t4 + (size_t)s1 * 32 + lane);
        float4 v2 = __ldg(t4 + (size_t)s2 * 32 + lane);
        float4 v3 = __ldg(t4 + (size_t)s3 * 32 + lane);
        a.x += v0.x * w0 + v1.x * w1 + v2.x * w2 + v3.x * w3;
        a.y += v0.y * w0 + v1.y * w1 + v2.y * w2 + v3.y * w3;
        a.z += v0.z * w0 + v1.z * w1 + v2.z * w2 + v3.z * w3;
        a.w += v0.w * w0 + v1.w * w1 + v2.w * w2 + v3.w * w3;
    }
    for (; e < e1; e++) {
        int s = __ldg(col + e);
        float wt = __ldg(w + e);
        float4 v = __ldg(t4 + (size_t)s * 32 + lane);
        a.x += v.x * wt;
        a.y += v.y * wt;
        a.z += v.z * wt;
        a.w += v.w * wt;
    }
    float4 b4 = *(const float4*)(bias + lane * 4);
    a.x += b4.x; a.y += b4.y; a.z += b4.z; a.w += b4.w;
    *((float4*)agg + (size_t)row * 32 + lane) = a;

    int c = lane * 4;
    atomicAdd(&ssum[c + 0], a.x);
    atomicAdd(&ssum[c + 1], a.y);
    atomicAdd(&ssum[c + 2], a.z);
    atomicAdd(&ssum[c + 3], a.w);
    atomicAdd(&ssq[c + 0], a.x * a.x);
    atomicAdd(&ssq[c + 1], a.y * a.y);
    atomicAdd(&ssq[c + 2], a.z * a.z);
    atomicAdd(&ssq[c + 3], a.w * a.w);
    __syncthreads();
    if (tid < HID) {
        asm volatile("red.global.add.f32 [%0], %1;" ::"l"(stats + tid), "f"(ssum[tid]) : "memory");
        asm volatile("red.global.add.f32 [%0], %1;" ::"l"(stats + HID + tid), "f"(ssq[tid]) : "memory");
    }
}

// ---------------- launch ----------------
extern "C" void kernel_launch(void* const* d_in, const int* in_sizes, int n_in,
                              void* d_out, int out_size) {
    const float* x = (const float*)d_in[0];
    const float* W_in = (const float*)d_in[1];
    const float* b_in = (const float*)d_in[2];
    const float* W_g = (const float*)d_in[3];
    const float* b_g = (const float*)d_in[4];
    const float* gamma = (const float*)d_in[5];
    const float* beta = (const float*)d_in[6];
    const float* W_out = (const float*)d_in[7];
    const float* b_out = (const float*)d_in[8];
    const void* ei = d_in[9];
    float* out = (float*)d_out;

    float *t, *agg, *h0, *acc, *dis, *stats, *w;
    uint32_t* wtf;
    int *cnt, *rowptr, *col, *blockoff;
    cudaGetSymbolAddress((void**)&t, g_t);
    cudaGetSymbolAddress((void**)&agg, g_agg);
    cudaGetSymbolAddress((void**)&h0, g_h0);
    cudaGetSymbolAddress((void**)&acc, g_acc);
    cudaGetSymbolAddress((void**)&dis, g_dis);
    cudaGetSymbolAddress((void**)&stats, g_stats);
    cudaGetSymbolAddress((void**)&wtf, g_wtf);
    cudaGetSymbolAddress((void**)&w, g_w);
    cudaGetSymbolAddress((void**)&cnt, g_cnt);
    cudaGetSymbolAddress((void**)&rowptr, g_rowptr);
    cudaGetSymbolAddress((void**)&col, g_col);
    cudaGetSymbolAddress((void**)&blockoff, g_blockoff);

    const int N = NNODES, E = NEDGES;
    const int gb = (N + 127) / 128;  // 391
    const size_t WG = 16384;         // packed words per 128x128 matrix

    // GEMM0 kept at profiled launch index 3
    detect_kernel<<<1, 256>>>((const long long*)ei);                              // 0
    zero_all_kernel<<<(N + 255) / 256, 256>>>(cnt, stats);                        // 1
    wpack_kernel<<<(5 * 8192 + 4096 + 255) / 256, 256>>>(W_in, W_g, W_out, wtf);  // 2
    // 3 (PROFILED): h0 = x @ W_in + b_in  (h0 doubles as skip)
    gemm_tc<128, 0, 1><<<dim3(gb, 2), 256>>>(x, wtf, b_in, nullptr, nullptr, nullptr,
                                             nullptr, nullptr, h0, N);
    count_kernel<<<(E + 255) / 256, 256>>>(ei, cnt, E);                           // 4
    scan1_kernel<<<SCAN_NBLK, 256>>>(cnt, rowptr, blockoff, dis);                 // 5
    scan2_kernel<<<1, 256>>>(blockoff);                                           // 6
    scan3_kernel<<<SCAN_NBLK, 256>>>(rowptr, blockoff);                           // 7
    zero_all_kernel<<<(N + 255) / 256, 256>>>(cnt, stats);                        // 8
    scatter_kernel<<<(E + 255) / 256, 256>>>(ei, dis, rowptr, cnt, col, w, E);    // 9

    // t0 = h0 @ W_g[0]
    gemm_tc<128, 0, 0><<<dim3(gb, 2), 256>>>(h0, wtf + WG, nullptr, nullptr, nullptr,
                                             nullptr, nullptr, nullptr, t, N);
    agg_stats_kernel<<<N / 8, 256>>>(t, dis, rowptr, col, w, b_g, agg, stats);
    // h1 = relu(norm0(agg0)); acc = h1; t1 = h1 @ W_g[1]
    gemm_tc<128, 1, 0><<<dim3(gb, 2), 256>>>(agg, wtf + 2 * WG, nullptr, stats, gamma,
                                             beta, nullptr, acc, t, N);
    agg_stats_kernel<<<N / 8, 256>>>(t, dis, rowptr, col, w, b_g + HID, agg, stats + 256);
    // h2 = relu(norm1(agg1) + 0.5*h0); acc += h2; t2 = h2 @ W_g[2]
    gemm_tc<128, 2, 0><<<dim3(gb, 2), 256>>>(agg, wtf + 3 * WG, nullptr, stats + 256,
                                             gamma + HID, beta + HID, h0, acc, t, N);
    agg_stats_kernel<<<N / 8, 256>>>(t, dis, rowptr, col, w, b_g + 2 * HID, agg, stats + 512);
    // h3 = relu(norm2(agg2)); acc += h3; t3 = h3 @ W_g[3]
    gemm_tc<128, 3, 0><<<dim3(gb, 2), 256>>>(agg, wtf + 4 * WG, nullptr, stats + 512,
                                             gamma + 2 * HID, beta + 2 * HID, nullptr, acc, t, N);
    agg_stats_kernel<<<N / 8, 256>>>(t, dis, rowptr, col, w, b_g + 3 * HID, agg, stats + 768);
    // out = (acc + relu(norm3(agg3) + 0.5*h0)) @ W_out + b_out
    gemm_tc<64, 4, 1><<<dim3(gb, 1), 256>>>(agg, wtf + 5 * WG, b_out, stats + 768,
                                            gamma + 3 * HID, beta + 3 * HID, h0, acc, out, N);
}

// round 11
// speedup vs baseline: 1.4633x; 1.4633x over previous
#include <cuda_runtime.h>
#include <cuda_fp16.h>
#include <cstdint>

#define NNODES 50000
#define NEDGES 600000
#define HID 128
#define OUTC 64
#define NGCN 4
#define EPSBN 1e-5f
#define SKIPW 0.5f

#define SCAN_CHUNK 200
#define SCAN_NBLK 250  // 250*200 = 50000

#define WTF_TOTAL (HID * HID * 5 + HID * OUTC)

// ---------------- scratch (static device globals; no runtime alloc) ----------------
__device__ __align__(16) __half g_t[NNODES * HID];  // t stored fp16 (gather traffic halved)
__device__ float g_agg[NNODES * HID];
__device__ float g_h0[NNODES * HID];  // input-linear output == skip
__device__ float g_acc[NNODES * HID];
__device__ float g_dis[NNODES];
__device__ float g_stats[NGCN * 2 * HID];
__device__ __align__(16) uint32_t g_wtf[WTF_TOTAL];  // weights, tf32, FRAGMENT-PACKED
__device__ int g_cnt[NNODES];
__device__ int g_rowptr[NNODES + 1];
__device__ int g_col[NEDGES];
__device__ float g_w[NEDGES];
__device__ int g_blockoff[SCAN_NBLK];
__device__ int g_is64;

// ---------------- edge-index dtype detection ----------------
__global__ void detect_kernel(const long long* __restrict__ ei64) {
    __shared__ int ok;
    if (threadIdx.x == 0) ok = 1;
    __syncthreads();
    for (int i = threadIdx.x; i < 4096; i += blockDim.x) {
        long long v = ei64[i];
        if (v < 0 || v >= NNODES) ok = 0;
    }
    __syncthreads();
    if (threadIdx.x == 0) g_is64 = ok;
}

__device__ __forceinline__ int load_idx(const void* ei, int pos, int is64) {
    if (is64) return (int)((const long long*)ei)[pos];
    return ((const int*)ei)[pos];
}

__device__ __forceinline__ uint32_t f2tf(float f) {
    uint32_t u;
    asm("cvt.rna.tf32.f32 %0, %1;" : "=r"(u) : "f"(f));
    return u;
}

// ---------------- pack all weights to tf32 in mma-fragment order ----------------
// For each (ks8, nb, lane): word0 = W[ks8*8 + (lane&3)][nb*8 + (lane>>2)]
//                           word1 = W[ks8*8 + (lane&3) + 4][nb*8 + (lane>>2)]
// Layout index: ((ks8*(BN/8) + nb)*32 + lane)*2 + {0,1}
__device__ __forceinline__ void wpack_one(const float* __restrict__ src,
                                          uint32_t* __restrict__ dst, int BN, int r) {
    int lane = r & 31;
    int blk = r >> 5;
    int nb = blk % (BN / 8);
    int ks8 = blk / (BN / 8);
    int k0 = ks8 * 8 + (lane & 3);
    int n = nb * 8 + (lane >> 2);
    dst[r * 2 + 0] = f2tf(src[(size_t)k0 * BN + n]);
    dst[r * 2 + 1] = f2tf(src[(size_t)(k0 + 4) * BN + n]);
}

__global__ void wpack_kernel(const float* __restrict__ W_in, const float* __restrict__ W_g,
                             const float* __restrict__ W_out, uint32_t* __restrict__ wtf) {
    int idx = blockIdx.x * blockDim.x + threadIdx.x;
    if (idx < 5 * 8192) {
        int m = idx / 8192;
        int r = idx % 8192;
        const float* src = (m == 0) ? W_in : (W_g + (size_t)(m - 1) * HID * HID);
        wpack_one(src, wtf + (size_t)m * 16384, 128, r);
    } else if (idx < 5 * 8192 + 4096) {
        int r = idx - 5 * 8192;
        wpack_one(W_out, wtf + (size_t)5 * 16384, 64, r);
    }
}

// ---------------- CSR build ----------------
__global__ void zero_all_kernel(int* cnt, float* stats) {
    int i = blockIdx.x * blockDim.x + threadIdx.x;
    if (i < NNODES) cnt[i] = 0;
    if (i < NGCN * 2 * HID) stats[i] = 0.0f;
}

__global__ void count_kernel(const void* __restrict__ ei, int* cnt, int E) {
    int e = blockIdx.x * blockDim.x + threadIdx.x;
    if (e < E) atomicAdd(&cnt[load_idx(ei, E + e, g_is64)], 1);
}

// inclusive scan within chunk; also compute dis from cnt
__global__ void scan1_kernel(const int* __restrict__ cnt, int* rowptr, int* blockoff,
                             float* dis) {
    __shared__ int s[256];
    int b = blockIdx.x, t = threadIdx.x;
    int i = b * SCAN_CHUNK + t;
    int v = (t < SCAN_CHUNK) ? cnt[i] : 0;
    if (t < SCAN_CHUNK) dis[i] = rsqrtf((float)v + 1.0f);  // self-loop degree
    s[t] = v;
    __syncthreads();
#pragma unroll
    for (int d = 1; d < 256; d <<= 1) {
        int add = (t >= d) ? s[t - d] : 0;
        __syncthreads();
        s[t] += add;
        __syncthreads();
    }
    if (t < SCAN_CHUNK) rowptr[i + 1] = s[t];
    if (t == 255) blockoff[b] = s[SCAN_CHUNK - 1];
}

__global__ void scan2_kernel(int* blockoff) {
    __shared__ int s[256];
    int t = threadIdx.x;
    int v = (t < SCAN_NBLK) ? blockoff[t] : 0;
    s[t] = v;
    __syncthreads();
#pragma unroll
    for (int d = 1; d < 256; d <<= 1) {
        int add = (t >= d) ? s[t - d] : 0;
        __syncthreads();
        s[t] += add;
        __syncthreads();
    }
    if (t < SCAN_NBLK) blockoff[t] = s[t] - v;  // exclusive
}

__global__ void scan3_kernel(int* rowptr, const int* __restrict__ blockoff) {
    int b = blockIdx.x, t = threadIdx.x;
    int i = b * SCAN_CHUNK + t;
    if (t < SCAN_CHUNK) rowptr[i + 1] += blockoff[b];
    if (b == 0 && t == 0) rowptr[0] = 0;
}

__global__ void scatter_kernel(const void* __restrict__ ei, const float* __restrict__ dis,
                               const int* __restrict__ rowptr, int* cnt,
                               int* col, float* w, int E) {
    int e = blockIdx.x * blockDim.x + threadIdx.x;
    if (e >= E) return;
    int is64 = g_is64;
    int src = load_idx(ei, e, is64);
    int dst = load_idx(ei, E + e, is64);
    int p = rowptr[dst] + atomicAdd(&cnt[dst], 1);
    col[p] = src;
    w[p] = dis[src] * dis[dst];
}

// ---------------- TF32 tensor-core GEMM (round-8 structure), optional fp16 C ----------------
// C[M,BN] = f(A)[M,128] @ Wtf[128,BN]   (Wtf fragment-packed tf32)
// AMODE 0: A plain
// AMODE 1: A = relu(agg*sc+sh);            acc  = A (init)
// AMODE 2: A = relu(agg*sc+sh + 0.5*skip); acc += A (red)
// AMODE 3: A = relu(agg*sc+sh);            acc += A (red)
// AMODE 4: A = accOld + relu(agg*sc+sh + 0.5*skip)   (output GEMM; no acc write)
// EPI 1: C += bias.  OUTH 1: C stored as __half.
#define MMA_TF32(d, a0, a1, a2, a3, b0, b1)                                    \
    asm volatile(                                                              \
        "mma.sync.aligned.m16n8k8.row.col.f32.tf32.tf32.f32 "                  \
        "{%0,%1,%2,%3}, {%4,%5,%6,%7}, {%8,%9}, {%0,%1,%2,%3};"                \
        : "+f"((d)[0]), "+f"((d)[1]), "+f"((d)[2]), "+f"((d)[3])               \
        : "r"(a0), "r"(a1), "r"(a2), "r"(a3), "r"(b0), "r"(b1))

template <int BN, int AMODE, int EPI, int OUTH>
__global__ __launch_bounds__(256, 2) void gemm_tc(
    const float* __restrict__ Ain, const uint32_t* __restrict__ Wtf,
    const float* __restrict__ bias, const float* __restrict__ stats,
    const float* __restrict__ gamma, const float* __restrict__ beta,
    const float* __restrict__ skipb, float* __restrict__ accb,
    void* __restrict__ Cv, int M) {
    constexpr int BM = 128, BK = 32;
    constexpr int NI = BN / 16;
    constexpr int NB8 = BN / 8;
    constexpr int ASLICE = 4096;  // 4 ks * 8 mb * 32 lanes * 4 slots
    constexpr bool HASSKIP = (AMODE == 2 || AMODE == 4);

    extern __shared__ uint32_t smem[];
    uint32_t* As0 = smem;            // fragment-major A slice (ping)
    uint32_t* As1 = As0 + ASLICE;    // pong
    uint32_t* Bs = As1 + ASLICE;     // whole W, fragment-packed: 1024*NB8 words
    float* sscale = (float*)(Bs + 1024 * NB8);
    float* sshift = sscale + HID;

    const int tid = threadIdx.x;
    const int lane = tid & 31;
    const int wid = tid >> 5;
    const int row0 = blockIdx.x * BM;
    const int warp_m = (wid & 3) * 32;
    const int warp_n = (wid >> 2) * (BN / 2);
    const int mb0 = (wid & 3) * 2;   // m16-block index base
    const int nb0 = (wid >> 2) * NI; // n8-block index base

    if (AMODE != 0 && tid < HID) {
        float invN = 1.0f / (float)M;
        float mean = stats[tid] * invN;
        float var = stats[HID + tid] * invN - mean * mean;
        float sc = gamma[tid] * rsqrtf(var + EPSBN);
        sscale[tid] = sc;
        sshift[tid] = beta[tid] - mean * sc;
    }

    // stage whole fragment-packed W: straight uint4 copies
    for (int i = tid; i < 256 * NB8; i += 256)
        ((uint4*)Bs)[i] = ((const uint4*)Wtf)[i];

    float acc[2][NI][4];
#pragma unroll
    for (int mi = 0; mi < 2; mi++)
#pragma unroll
        for (int ni = 0; ni < NI; ni++)
#pragma unroll
            for (int j = 0; j < 4; j++) acc[mi][ni][j] = 0.0f;

    float4 pa[4], psk[4], pac[4];

    auto ldA = [&](int kb) {
#pragma unroll
        for (int u = 0; u < 4; u++) {
            int i = tid + u * 256;
            int r = i >> 3;
            int kc = (i & 7) * 4;
            int gr = row0 + r;
            size_t off = (size_t)gr * HID + kb * BK + kc;
            float4 z = make_float4(0.f, 0.f, 0.f, 0.f);
            pa[u] = (gr < M) ? *(const float4*)(Ain + off) : z;
            if (HASSKIP) psk[u] = (gr < M) ? *(const float4*)(skipb + off) : z;
            if (AMODE == 4) pac[u] = (gr < M) ? *(const float4*)(accb + off) : z;
        }
    };

    // write v into fragment-major slice
    auto storeA = [&](int kb, uint32_t* buf) {
#pragma unroll
        for (int u = 0; u < 4; u++) {
            int i = tid + u * 256;
            int r = i >> 3;
            int kc = (i & 7) * 4;
            int gr = row0 + r;
            int c = kb * BK + kc;
            float4 v = pa[u];
            if (AMODE != 0) {
                v.x = v.x * sscale[c + 0] + sshift[c + 0];
                v.y = v.y * sscale[c + 1] + sshift[c + 1];
                v.z = v.z * sscale[c + 2] + sshift[c + 2];
                v.w = v.w * sscale[c + 3] + sshift[c + 3];
                if (HASSKIP) {
                    v.x += SKIPW * psk[u].x;
                    v.y += SKIPW * psk[u].y;
                    v.z += SKIPW * psk[u].z;
                    v.w += SKIPW * psk[u].w;
                }
                v.x = fmaxf(v.x, 0.f);
                v.y = fmaxf(v.y, 0.f);
                v.z = fmaxf(v.z, 0.f);
                v.w = fmaxf(v.w, 0.f);
                if (AMODE == 1 && gr < M)
                    *(float4*)(accb + (size_t)gr * HID + c) = v;
                if ((AMODE == 2 || AMODE == 3) && gr < M)
                    asm volatile("red.global.add.v4.f32 [%0], {%1,%2,%3,%4};" ::
                                     "l"(accb + (size_t)gr * HID + c),
                                 "f"(v.x), "f"(v.y), "f"(v.z), "f"(v.w)
                                 : "memory");
                if (AMODE == 4) {
                    v.x += pac[u].x;
                    v.y += pac[u].y;
                    v.z += pac[u].z;
                    v.w += pac[u].w;
                }
            }
            int mb = r >> 4;
            int rm = r & 15;
            int laneg = (rm & 7) * 4;
            int slm = (rm >= 8) ? 1 : 0;
            int ks = kc >> 3;
            int khi = (kc & 7) ? 2 : 0;
            uint32_t* base = buf + ((ks * 8 + mb) * 32) * 4;
            float vv[4] = {v.x, v.y, v.z, v.w};
#pragma unroll
            for (int j = 0; j < 4; j++)
                base[(laneg + j) * 4 + khi + slm] = f2tf(vv[j]);
        }
    };

    ldA(0);
    storeA(0, As0);
    __syncthreads();  // covers Bs staging + As0

    for (int kb = 0; kb < HID / BK; kb++) {
        uint32_t* cur = (kb & 1) ? As1 : As0;
        uint32_t* nxt = (kb & 1) ? As0 : As1;
        if (kb < HID / BK - 1) ldA(kb + 1);  // LDG latency overlapped with MMAs
#pragma unroll
        for (int ks = 0; ks < BK / 8; ks++) {
            uint4 af0 = *(const uint4*)(cur + ((ks * 8 + mb0) * 32 + lane) * 4);
            uint4 af1 = *(const uint4*)(cur + ((ks * 8 + mb0 + 1) * 32 + lane) * 4);
            const int ksg = kb * 4 + ks;
            uint2 bf[NI];
#pragma unroll
            for (int ni = 0; ni < NI; ni++)
                bf[ni] = *(const uint2*)(Bs + ((ksg * NB8 + nb0 + ni) * 32 + lane) * 2);
#pragma unroll
            for (int ni = 0; ni < NI; ni++) {
                MMA_TF32(acc[0][ni], af0.x, af0.y, af0.z, af0.w, bf[ni].x, bf[ni].y);
                MMA_TF32(acc[1][ni], af1.x, af1.y, af1.z, af1.w, bf[ni].x, bf[ni].y);
            }
        }
        if (kb < HID / BK - 1) storeA(kb + 1, nxt);
        __syncthreads();
    }

#pragma unroll
    for (int mi = 0; mi < 2; mi++) {
        int rbase = row0 + warp_m + mi * 16 + (lane >> 2);
#pragma unroll
        for (int half = 0; half < 2; half++) {
            int r = rbase + half * 8;
            if (r >= M) continue;
#pragma unroll
            for (int ni = 0; ni < NI; ni++) {
                int c = warp_n + ni * 8 + (lane & 3) * 2;
                float v0 = acc[mi][ni][half * 2 + 0];
                float v1 = acc[mi][ni][half * 2 + 1];
                if (EPI) {
                    v0 += bias[c];
                    v1 += bias[c + 1];
                }
                if (OUTH) {
                    __half2 hv = __floats2half2_rn(v0, v1);
                    *(__half2*)((__half*)Cv + (size_t)r * BN + c) = hv;
                } else {
                    *(float2*)((float*)Cv + (size_t)r * BN + c) = make_float2(v0, v1);
                }
            }
        }
    }
}

// ---------------- CSR aggregation (fp16 t gather) + fused BN stats ----------------
// one warp per dst row; lane covers cols lane*4..lane*4+3 (one uint2 = 4 halfs)
__global__ __launch_bounds__(256) void agg_stats_kernel(
    const __half* __restrict__ t, const float* __restrict__ dis,
    const int* __restrict__ rowptr, const int* __restrict__ col,
    const float* __restrict__ w, const float* __restrict__ bias,
    float* __restrict__ agg, float* __restrict__ stats) {
    __shared__ float ssum[HID];
    __shared__ float ssq[HID];
    const int tid = threadIdx.x;
    const int lane = tid & 31;
    const int widx = tid >> 5;
    if (tid < HID) {
        ssum[tid] = 0.0f;
        ssq[tid] = 0.0f;
    }
    __syncthreads();

    const int row = blockIdx.x * 8 + widx;  // grid = NNODES/8
    const uint2* t2 = (const uint2*)t;      // 4 halfs per uint2; 32 uint2 per row

    auto load4 = [&](int r) -> float4 {
        uint2 u = __ldg(t2 + (size_t)r * 32 + lane);
        float2 lo = __half22float2(*(__half2*)&u.x);
        float2 hi = __half22float2(*(__half2*)&u.y);
        return make_float4(lo.x, lo.y, hi.x, hi.y);
    };

    float d = dis[row];
    float sn = d * d;
    float4 a = load4(row);
    a.x *= sn; a.y *= sn; a.z *= sn; a.w *= sn;

    const int e0 = rowptr[row];
    const int e1 = rowptr[row + 1];
    int e = e0;
    for (; e + 4 <= e1; e += 4) {
        int s0 = __ldg(col + e + 0), s1 = __ldg(col + e + 1);
        int s2 = __ldg(col + e + 2), s3 = __ldg(col + e + 3);
        float w0 = __ldg(w + e + 0), w1 = __ldg(w + e + 1);
        float w2 = __ldg(w + e + 2), w3 = __ldg(w + e + 3);
        float4 v0 = load4(s0);
        float4 v1 = load4(s1);
        float4 v2 = load4(s2);
        float4 v3 = load4(s3);
        a.x += v0.x * w0 + v1.x * w1 + v2.x * w2 + v3.x * w3;
        a.y += v0.y * w0 + v1.y * w1 + v2.y * w2 + v3.y * w3;
        a.z += v0.z * w0 + v1.z * w1 + v2.z * w2 + v3.z * w3;
        a.w += v0.w * w0 + v1.w * w1 + v2.w * w2 + v3.w * w3;
    }
    for (; e < e1; e++) {
        int s = __ldg(col + e);
        float wt = __ldg(w + e);
        float4 v = load4(s);
        a.x += v.x * wt;
        a.y += v.y * wt;
        a.z += v.z * wt;
        a.w += v.w * wt;
    }
    float4 b4 = *(const float4*)(bias + lane * 4);
    a.x += b4.x; a.y += b4.y; a.z += b4.z; a.w += b4.w;
    *((float4*)agg + (size_t)row * 32 + lane) = a;

    int c = lane * 4;
    atomicAdd(&ssum[c + 0], a.x);
    atomicAdd(&ssum[c + 1], a.y);
    atomicAdd(&ssum[c + 2], a.z);
    atomicAdd(&ssum[c + 3], a.w);
    atomicAdd(&ssq[c + 0], a.x * a.x);
    atomicAdd(&ssq[c + 1], a.y * a.y);
    atomicAdd(&ssq[c + 2], a.z * a.z);
    atomicAdd(&ssq[c + 3], a.w * a.w);
    __syncthreads();
    if (tid < HID) {
        asm volatile("red.global.add.f32 [%0], %1;" ::"l"(stats + tid), "f"(ssum[tid]) : "memory");
        asm volatile("red.global.add.f32 [%0], %1;" ::"l"(stats + HID + tid), "f"(ssq[tid]) : "memory");
    }
}

// ---------------- launch ----------------
extern "C" void kernel_launch(void* const* d_in, const int* in_sizes, int n_in,
                              void* d_out, int out_size) {
    const float* x = (const float*)d_in[0];
    const float* W_in = (const float*)d_in[1];
    const float* b_in = (const float*)d_in[2];
    const float* W_g = (const float*)d_in[3];
    const float* b_g = (const float*)d_in[4];
    const float* gamma = (const float*)d_in[5];
    const float* beta = (const float*)d_in[6];
    const float* W_out = (const float*)d_in[7];
    const float* b_out = (const float*)d_in[8];
    const void* ei = d_in[9];
    float* out = (float*)d_out;

    float *agg, *h0, *acc, *dis, *stats, *w;
    __half* t;
    uint32_t* wtf;
    int *cnt, *rowptr, *col, *blockoff;
    cudaGetSymbolAddress((void**)&t, g_t);
    cudaGetSymbolAddress((void**)&agg, g_agg);
    cudaGetSymbolAddress((void**)&h0, g_h0);
    cudaGetSymbolAddress((void**)&acc, g_acc);
    cudaGetSymbolAddress((void**)&dis, g_dis);
    cudaGetSymbolAddress((void**)&stats, g_stats);
    cudaGetSymbolAddress((void**)&wtf, g_wtf);
    cudaGetSymbolAddress((void**)&w, g_w);
    cudaGetSymbolAddress((void**)&cnt, g_cnt);
    cudaGetSymbolAddress((void**)&rowptr, g_rowptr);
    cudaGetSymbolAddress((void**)&col, g_col);
    cudaGetSymbolAddress((void**)&blockoff, g_blockoff);

    const int N = NNODES, E = NEDGES;

    // dyn smem: 2*ASLICE(4096) + Bs(1024*NB8) + scale/shift(256) words
    const int SH128 = (2 * 4096 + 1024 * 16 + 2 * HID) * 4;  // 99328
    const int SH64 = (2 * 4096 + 1024 * 8 + 2 * HID) * 4;    // 66560
    cudaFuncSetAttribute(gemm_tc<128, 0, 1, 0>, cudaFuncAttributeMaxDynamicSharedMemorySize, SH128);
    cudaFuncSetAttribute(gemm_tc<128, 0, 0, 1>, cudaFuncAttributeMaxDynamicSharedMemorySize, SH128);
    cudaFuncSetAttribute(gemm_tc<128, 1, 0, 1>, cudaFuncAttributeMaxDynamicSharedMemorySize, SH128);
    cudaFuncSetAttribute(gemm_tc<128, 2, 0, 1>, cudaFuncAttributeMaxDynamicSharedMemorySize, SH128);
    cudaFuncSetAttribute(gemm_tc<128, 3, 0, 1>, cudaFuncAttributeMaxDynamicSharedMemorySize, SH128);
    cudaFuncSetAttribute(gemm_tc<64, 4, 1, 0>, cudaFuncAttributeMaxDynamicSharedMemorySize, SH64);

    const int gb = (N + 127) / 128;  // 391
    const size_t WG = 16384;         // packed words per 128x128 matrix

    // GEMM0 kept at profiled launch index 3
    detect_kernel<<<1, 256>>>((const long long*)ei);                              // 0
    zero_all_kernel<<<(N + 255) / 256, 256>>>(cnt, stats);                        // 1
    wpack_kernel<<<(5 * 8192 + 4096 + 255) / 256, 256>>>(W_in, W_g, W_out, wtf);  // 2
    // 3 (PROFILED): h0 = x @ W_in + b_in  (h0 doubles as skip)
    gemm_tc<128, 0, 1, 0><<<gb, 256, SH128>>>(x, wtf, b_in, nullptr, nullptr, nullptr,
                                              nullptr, nullptr, h0, N);
    count_kernel<<<(E + 255) / 256, 256>>>(ei, cnt, E);                           // 4
    scan1_kernel<<<SCAN_NBLK, 256>>>(cnt, rowptr, blockoff, dis);                 // 5
    scan2_kernel<<<1, 256>>>(blockoff);                                           // 6
    scan3_kernel<<<SCAN_NBLK, 256>>>(rowptr, blockoff);                           // 7
    zero_all_kernel<<<(N + 255) / 256, 256>>>(cnt, stats);                        // 8
    scatter_kernel<<<(E + 255) / 256, 256>>>(ei, dis, rowptr, cnt, col, w, E);    // 9

    // t0 = h0 @ W_g[0]  (fp16 out)
    gemm_tc<128, 0, 0, 1><<<gb, 256, SH128>>>(h0, wtf + WG, nullptr, nullptr, nullptr,
                                              nullptr, nullptr, nullptr, t, N);
    agg_stats_kernel<<<N / 8, 256>>>(t, dis, rowptr, col, w, b_g, agg, stats);
    // h1 = relu(norm0(agg0)); acc = h1; t1 = h1 @ W_g[1]
    gemm_tc<128, 1, 0, 1><<<gb, 256, SH128>>>(agg, wtf + 2 * WG, nullptr, stats, gamma,
                                              beta, nullptr, acc, t, N);
    agg_stats_kernel<<<N / 8, 256>>>(t, dis, rowptr, col, w, b_g + HID, agg, stats + 256);
    // h2 = relu(norm1(agg1) + 0.5*h0); acc += h2; t2 = h2 @ W_g[2]
    gemm_tc<128, 2, 0, 1><<<gb, 256, SH128>>>(agg, wtf + 3 * WG, nullptr, stats + 256,
                                              gamma + HID, beta + HID, h0, acc, t, N);
    agg_stats_kernel<<<N / 8, 256>>>(t, dis, rowptr, col, w, b_g + 2 * HID, agg, stats + 512);
    // h3 = relu(norm2(agg2)); acc += h3; t3 = h3 @ W_g[3]
    gemm_tc<128, 3, 0, 1><<<gb, 256, SH128>>>(agg, wtf + 4 * WG, nullptr, stats + 512,
                                              gamma + 2 * HID, beta + 2 * HID, nullptr, acc, t, N);
    agg_stats_kernel<<<N / 8, 256>>>(t, dis, rowptr, col, w, b_g + 3 * HID, agg, stats + 768);
    // out = (acc + relu(norm3(agg3) + 0.5*h0)) @ W_out + b_out
    gemm_tc<64, 4, 1, 0><<<gb, 256, SH64>>>(agg, wtf + 5 * WG, b_out, stats + 768,
                                            gamma + 3 * HID, beta + 3 * HID, h0, acc, out, N);
}

// round 13
// speedup vs baseline: 1.7608x; 1.2033x over previous
#include <cuda_runtime.h>
#include <cuda_fp16.h>
#include <cstdint>

#define NNODES 50000
#define NEDGES 600000
#define HID 128
#define OUTC 64
#define NGCN 4
#define EPSBN 1e-5f
#define SKIPW 0.5f

#define SCAN_CHUNK 200
#define SCAN_NBLK 250  // 250*200 = 50000

// fp16 fragment-packed weights: 128-wide matrix = 8192 words, 64-wide = 4096
#define WTF_TOTAL (8192 * 5 + 4096)

// ---------------- scratch (static device globals; no runtime alloc) ----------------
__device__ __align__(16) __half g_t[NNODES * HID];  // t stored fp16
__device__ float g_agg[NNODES * HID];
__device__ float g_h0[NNODES * HID];  // input-linear output == skip
__device__ float g_acc[NNODES * HID];
__device__ float g_dis[NNODES];
__device__ float g_stats[NGCN * 2 * HID];
__device__ __align__(16) uint32_t g_wtf[WTF_TOTAL];  // weights fp16, FRAGMENT-PACKED (m16n8k16)
__device__ int g_cnt[NNODES];
__device__ int g_rowptr[NNODES + 1];
__device__ int g_col[NEDGES];
__device__ float g_w[NEDGES];
__device__ int g_blockoff[SCAN_NBLK];
__device__ int g_is64;

// ---------------- edge-index dtype detection ----------------
__global__ void detect_kernel(const long long* __restrict__ ei64) {
    __shared__ int ok;
    if (threadIdx.x == 0) ok = 1;
    __syncthreads();
    for (int i = threadIdx.x; i < 4096; i += blockDim.x) {
        long long v = ei64[i];
        if (v < 0 || v >= NNODES) ok = 0;
    }
    __syncthreads();
    if (threadIdx.x == 0) g_is64 = ok;
}

__device__ __forceinline__ int load_idx(const void* ei, int pos, int is64) {
    if (is64) return (int)((const long long*)ei)[pos];
    return ((const int*)ei)[pos];
}

// ---------------- pack all weights to fp16 in m16n8k16 B-fragment order ----------------
// unit r: lane = r&31, blk = r>>5, nb = blk % (BN/8), ks16 = blk / (BN/8)
//   k0 = ks16*16 + (lane&3)*2, n = nb*8 + (lane>>2)
//   word0 = half2(W[k0][n],   W[k0+1][n])
//   word1 = half2(W[k0+8][n], W[k0+9][n])
__device__ __forceinline__ void wpack_one(const float* __restrict__ src,
                                          uint32_t* __restrict__ dst, int BN, int r) {
    int lane = r & 31;
    int blk = r >> 5;
    int nb = blk % (BN / 8);
    int ks16 = blk / (BN / 8);
    int k0 = ks16 * 16 + (lane & 3) * 2;
    int n = nb * 8 + (lane >> 2);
    __half2 w0 = __floats2half2_rn(src[(size_t)k0 * BN + n], src[(size_t)(k0 + 1) * BN + n]);
    __half2 w1 = __floats2half2_rn(src[(size_t)(k0 + 8) * BN + n], src[(size_t)(k0 + 9) * BN + n]);
    dst[r * 2 + 0] = *(uint32_t*)&w0;
    dst[r * 2 + 1] = *(uint32_t*)&w1;
}

__global__ void wpack_kernel(const float* __restrict__ W_in, const float* __restrict__ W_g,
                             const float* __restrict__ W_out, uint32_t* __restrict__ wtf) {
    int idx = blockIdx.x * blockDim.x + threadIdx.x;
    // five 128x128 matrices: 4096 pack-units each; W_out: 2048 units
    if (idx < 5 * 4096) {
        int m = idx / 4096;
        int r = idx % 4096;
        const float* src = (m == 0) ? W_in : (W_g + (size_t)(m - 1) * HID * HID);
        wpack_one(src, wtf + (size_t)m * 8192, 128, r);
    } else if (idx < 5 * 4096 + 2048) {
        int r = idx - 5 * 4096;
        wpack_one(W_out, wtf + (size_t)5 * 8192, 64, r);
    }
}

// ---------------- CSR build ----------------
__global__ void zero_all_kernel(int* cnt, float* stats) {
    int i = blockIdx.x * blockDim.x + threadIdx.x;
    if (i < NNODES) cnt[i] = 0;
    if (i < NGCN * 2 * HID) stats[i] = 0.0f;
}

__global__ void count_kernel(const void* __restrict__ ei, int* cnt, int E) {
    int e = blockIdx.x * blockDim.x + threadIdx.x;
    if (e < E) atomicAdd(&cnt[load_idx(ei, E + e, g_is64)], 1);
}

// inclusive scan within chunk; also compute dis from cnt
__global__ void scan1_kernel(const int* __restrict__ cnt, int* rowptr, int* blockoff,
                             float* dis) {
    __shared__ int s[256];
    int b = blockIdx.x, t = threadIdx.x;
    int i = b * SCAN_CHUNK + t;
    int v = (t < SCAN_CHUNK) ? cnt[i] : 0;
    if (t < SCAN_CHUNK) dis[i] = rsqrtf((float)v + 1.0f);  // self-loop degree
    s[t] = v;
    __syncthreads();
#pragma unroll
    for (int d = 1; d < 256; d <<= 1) {
        int add = (t >= d) ? s[t - d] : 0;
        __syncthreads();
        s[t] += add;
        __syncthreads();
    }
    if (t < SCAN_CHUNK) rowptr[i + 1] = s[t];
    if (t == 255) blockoff[b] = s[SCAN_CHUNK - 1];
}

__global__ void scan2_kernel(int* blockoff) {
    __shared__ int s[256];
    int t = threadIdx.x;
    int v = (t < SCAN_NBLK) ? blockoff[t] : 0;
    s[t] = v;
    __syncthreads();
#pragma unroll
    for (int d = 1; d < 256; d <<= 1) {
        int add = (t >= d) ? s[t - d] : 0;
        __syncthreads();
        s[t] += add;
        __syncthreads();
    }
    if (t < SCAN_NBLK) blockoff[t] = s[t] - v;  // exclusive
}

__global__ void scan3_kernel(int* rowptr, const int* __restrict__ blockoff) {
    int b = blockIdx.x, t = threadIdx.x;
    int i = b * SCAN_CHUNK + t;
    if (t < SCAN_CHUNK) rowptr[i + 1] += blockoff[b];
    if (b == 0 && t == 0) rowptr[0] = 0;
}

__global__ void scatter_kernel(const void* __restrict__ ei, const float* __restrict__ dis,
                               const int* __restrict__ rowptr, int* cnt,
                               int* col, float* w, int E) {
    int e = blockIdx.x * blockDim.x + threadIdx.x;
    if (e >= E) return;
    int is64 = g_is64;
    int src = load_idx(ei, e, is64);
    int dst = load_idx(ei, E + e, is64);
    int p = rowptr[dst] + atomicAdd(&cnt[dst], 1);
    col[p] = src;
    w[p] = dis[src] * dis[dst];
}

// ---------------- FP16 tensor-core GEMM (m16n8k16, fp32 accumulate) ----------------
// C[M,BN] = f(A)[M,128] @ Wh[128,BN]   (Wh fp16 fragment-packed)
// AMODE 0: A plain
// AMODE 1: A = relu(agg*sc+sh);            acc  = A (init)
// AMODE 2: A = relu(agg*sc+sh + 0.5*skip); acc += A (red)
// AMODE 3: A = relu(agg*sc+sh);            acc += A (red)
// AMODE 4: A = accOld + relu(agg*sc+sh + 0.5*skip)   (output GEMM; no acc write)
// EPI 1: C += bias.  OUTH 1: C stored as __half.
#define MMA_F16(d, a0, a1, a2, a3, b0, b1)                                     \
    asm volatile(                                                              \
        "mma.sync.aligned.m16n8k16.row.col.f32.f16.f16.f32 "                   \
        "{%0,%1,%2,%3}, {%4,%5,%6,%7}, {%8,%9}, {%0,%1,%2,%3};"                \
        : "+f"((d)[0]), "+f"((d)[1]), "+f"((d)[2]), "+f"((d)[3])               \
        : "r"(a0), "r"(a1), "r"(a2), "r"(a3), "r"(b0), "r"(b1))

template <int BN, int AMODE, int EPI, int OUTH>
__global__ __launch_bounds__(256, 2) void gemm_tc(
    const float* __restrict__ Ain, const uint32_t* __restrict__ Wtf,
    const float* __restrict__ bias, const float* __restrict__ stats,
    const float* __restrict__ gamma, const float* __restrict__ beta,
    const float* __restrict__ skipb, float* __restrict__ accb,
    void* __restrict__ Cv, int M) {
    constexpr int BM = 128, BK = 32;
    constexpr int NI = BN / 16;
    constexpr int NB8 = BN / 8;
    constexpr int ASLICE = 2048;  // 2 ks16 * 8 mb * 32 lanes * 4 slots (half2 words)
    constexpr int BSWORDS = 8 * NB8 * 32 * 2;  // whole W fp16-packed
    constexpr bool HASSKIP = (AMODE == 2 || AMODE == 4);

    extern __shared__ uint32_t smem[];
    uint32_t* As0 = smem;            // fragment-major A slice (ping)
    uint32_t* As1 = As0 + ASLICE;    // pong
    uint32_t* Bs = As1 + ASLICE;     // whole W, fragment-packed
    float* sscale = (float*)(Bs + BSWORDS);
    float* sshift = sscale + HID;

    const int tid = threadIdx.x;
    const int lane = tid & 31;
    const int wid = tid >> 5;
    const int row0 = blockIdx.x * BM;
    const int warp_m = (wid & 3) * 32;
    const int warp_n = (wid >> 2) * (BN / 2);
    const int mb0 = (wid & 3) * 2;   // m16-block index base
    const int nb0 = (wid >> 2) * NI; // n8-block index base

    if (AMODE != 0 && tid < HID) {
        float invN = 1.0f / (float)M;
        float mean = stats[tid] * invN;
        float var = stats[HID + tid] * invN - mean * mean;
        float sc = gamma[tid] * rsqrtf(var + EPSBN);
        sscale[tid] = sc;
        sshift[tid] = beta[tid] - mean * sc;
    }

    // stage whole fragment-packed W: straight uint4 copies
    for (int i = tid; i < BSWORDS / 4; i += 256)
        ((uint4*)Bs)[i] = ((const uint4*)Wtf)[i];

    float acc[2][NI][4];
#pragma unroll
    for (int mi = 0; mi < 2; mi++)
#pragma unroll
        for (int ni = 0; ni < NI; ni++)
#pragma unroll
            for (int j = 0; j < 4; j++) acc[mi][ni][j] = 0.0f;

    float4 pa[4], psk[4], pac[4];

    auto ldA = [&](int kb) {
#pragma unroll
        for (int u = 0; u < 4; u++) {
            int i = tid + u * 256;
            int r = i >> 3;
            int kc = (i & 7) * 4;
            int gr = row0 + r;
            size_t off = (size_t)gr * HID + kb * BK + kc;
            float4 z = make_float4(0.f, 0.f, 0.f, 0.f);
            pa[u] = (gr < M) ? *(const float4*)(Ain + off) : z;
            if (HASSKIP) psk[u] = (gr < M) ? *(const float4*)(skipb + off) : z;
            if (AMODE == 4) pac[u] = (gr < M) ? *(const float4*)(accb + off) : z;
        }
    };

    // write v (4 consecutive cols) into m16n8k16 A-fragment positions as 2 half2 words
    auto storeA = [&](int kb, uint32_t* buf) {
#pragma unroll
        for (int u = 0; u < 4; u++) {
            int i = tid + u * 256;
            int r = i >> 3;
            int kc = (i & 7) * 4;  // 0,4,...,28
            int gr = row0 + r;
            int c = kb * BK + kc;
            float4 v = pa[u];
            if (AMODE != 0) {
                v.x = v.x * sscale[c + 0] + sshift[c + 0];
                v.y = v.y * sscale[c + 1] + sshift[c + 1];
                v.z = v.z * sscale[c + 2] + sshift[c + 2];
                v.w = v.w * sscale[c + 3] + sshift[c + 3];
                if (HASSKIP) {
                    v.x += SKIPW * psk[u].x;
                    v.y += SKIPW * psk[u].y;
                    v.z += SKIPW * psk[u].z;
                    v.w += SKIPW * psk[u].w;
                }
                v.x = fmaxf(v.x, 0.f);
                v.y = fmaxf(v.y, 0.f);
                v.z = fmaxf(v.z, 0.f);
                v.w = fmaxf(v.w, 0.f);
                if (AMODE == 1 && gr < M)
                    *(float4*)(accb + (size_t)gr * HID + c) = v;
                if ((AMODE == 2 || AMODE == 3) && gr < M)
                    asm volatile("red.global.add.v4.f32 [%0], {%1,%2,%3,%4};" ::
                                     "l"(accb + (size_t)gr * HID + c),
                                 "f"(v.x), "f"(v.y), "f"(v.z), "f"(v.w)
                                 : "memory");
                if (AMODE == 4) {
                    v.x += pac[u].x;
                    v.y += pac[u].y;
                    v.z += pac[u].z;
                    v.w += pac[u].w;
                }
            }
            int mb = r >> 4;
            int rm = r & 15;
            int ks = kc >> 4;     // 0 or 1 within BK=32 slice
            int kin = kc & 15;    // 0,4,8,12
            int lane0 = (rm & 7) * 4 + ((kin >> 1) & 3);
            int lane1 = (rm & 7) * 4 + (((kin >> 1) + 1) & 3);
            int slot = ((kin & 8) ? 2 : 0) + ((rm & 8) ? 1 : 0);
            uint32_t* base = buf + ((ks * 8 + mb) * 32) * 4;
            __half2 h0 = __floats2half2_rn(v.x, v.y);
            __half2 h1 = __floats2half2_rn(v.z, v.w);
            base[lane0 * 4 + slot] = *(uint32_t*)&h0;
            base[lane1 * 4 + slot] = *(uint32_t*)&h1;
        }
    };

    ldA(0);
    // RACE FIX: sscale/sshift (written by tid<128) must be visible to ALL
    // threads before storeA(0) reads them. This barrier also orders Bs staging.
    __syncthreads();
    storeA(0, As0);
    __syncthreads();  // As0 visible to consumers

    for (int kb = 0; kb < HID / BK; kb++) {
        uint32_t* cur = (kb & 1) ? As1 : As0;
        uint32_t* nxt = (kb & 1) ? As0 : As1;
        if (kb < HID / BK - 1) ldA(kb + 1);  // LDG latency overlapped with MMAs
#pragma unroll
        for (int ks = 0; ks < 2; ks++) {  // two k16 steps per BK=32 slice
            uint4 af0 = *(const uint4*)(cur + ((ks * 8 + mb0) * 32 + lane) * 4);
            uint4 af1 = *(const uint4*)(cur + ((ks * 8 + mb0 + 1) * 32 + lane) * 4);
            const int ksg = kb * 2 + ks;  // global k16 index 0..7
            uint2 bf[NI];
#pragma unroll
            for (int ni = 0; ni < NI; ni++)
                bf[ni] = *(const uint2*)(Bs + ((ksg * NB8 + nb0 + ni) * 32 + lane) * 2);
#pragma unroll
            for (int ni = 0; ni < NI; ni++) {
                MMA_F16(acc[0][ni], af0.x, af0.y, af0.z, af0.w, bf[ni].x, bf[ni].y);
                MMA_F16(acc[1][ni], af1.x, af1.y, af1.z, af1.w, bf[ni].x, bf[ni].y);
            }
        }
        if (kb < HID / BK - 1) storeA(kb + 1, nxt);
        __syncthreads();
    }

#pragma unroll
    for (int mi = 0; mi < 2; mi++) {
        int rbase = row0 + warp_m + mi * 16 + (lane >> 2);
#pragma unroll
        for (int half = 0; half < 2; half++) {
            int r = rbase + half * 8;
            if (r >= M) continue;
#pragma unroll
            for (int ni = 0; ni < NI; ni++) {
                int c = warp_n + ni * 8 + (lane & 3) * 2;
                float v0 = acc[mi][ni][half * 2 + 0];
                float v1 = acc[mi][ni][half * 2 + 1];
                if (EPI) {
                    v0 += bias[c];
                    v1 += bias[c + 1];
                }
                if (OUTH) {
                    __half2 hv = __floats2half2_rn(v0, v1);
                    *(__half2*)((__half*)Cv + (size_t)r * BN + c) = hv;
                } else {
                    *(float2*)((float*)Cv + (size_t)r * BN + c) = make_float2(v0, v1);
                }
            }
        }
    }
}

// ---------------- CSR aggregation (fp16 t gather) + fused BN stats ----------------
// one warp per dst row; lane covers cols lane*4..lane*4+3 (one uint2 = 4 halfs)
__global__ __launch_bounds__(256) void agg_stats_kernel(
    const __half* __restrict__ t, const float* __restrict__ dis,
    const int* __restrict__ rowptr, const int* __restrict__ col,
    const float* __restrict__ w, const float* __restrict__ bias,
    float* __restrict__ agg, float* __restrict__ stats) {
    __shared__ float ssum[HID];
    __shared__ float ssq[HID];
    const int tid = threadIdx.x;
    const int lane = tid & 31;
    const int widx = tid >> 5;
    if (tid < HID) {
        ssum[tid] = 0.0f;
        ssq[tid] = 0.0f;
    }
    __syncthreads();

    const int row = blockIdx.x * 8 + widx;  // grid = NNODES/8
    const uint2* t2 = (const uint2*)t;      // 4 halfs per uint2; 32 uint2 per row

    auto load4 = [&](int r) -> float4 {
        uint2 u = __ldg(t2 + (size_t)r * 32 + lane);
        float2 lo = __half22float2(*(__half2*)&u.x);
        float2 hi = __half22float2(*(__half2*)&u.y);
        return make_float4(lo.x, lo.y, hi.x, hi.y);
    };

    float d = dis[row];
    float sn = d * d;
    float4 a = load4(row);
    a.x *= sn; a.y *= sn; a.z *= sn; a.w *= sn;

    const int e0 = rowptr[row];
    const int e1 = rowptr[row + 1];
    int e = e0;
    for (; e + 4 <= e1; e += 4) {
        int s0 = __ldg(col + e + 0), s1 = __ldg(col + e + 1);
        int s2 = __ldg(col + e + 2), s3 = __ldg(col + e + 3);
        float w0 = __ldg(w + e + 0), w1 = __ldg(w + e + 1);
        float w2 = __ldg(w + e + 2), w3 = __ldg(w + e + 3);
        float4 v0 = load4(s0);
        float4 v1 = load4(s1);
        float4 v2 = load4(s2);
        float4 v3 = load4(s3);
        a.x += v0.x * w0 + v1.x * w1 + v2.x * w2 + v3.x * w3;
        a.y += v0.y * w0 + v1.y * w1 + v2.y * w2 + v3.y * w3;
        a.z += v0.z * w0 + v1.z * w1 + v2.z * w2 + v3.z * w3;
        a.w += v0.w * w0 + v1.w * w1 + v2.w * w2 + v3.w * w3;
    }
    for (; e < e1; e++) {
        int s = __ldg(col + e);
        float wt = __ldg(w + e);
        float4 v = load4(s);
        a.x += v.x * wt;
        a.y += v.y * wt;
        a.z += v.z * wt;
        a.w += v.w * wt;
    }
    float4 b4 = *(const float4*)(bias + lane * 4);
    a.x += b4.x; a.y += b4.y; a.z += b4.z; a.w += b4.w;
    *((float4*)agg + (size_t)row * 32 + lane) = a;

    int c = lane * 4;
    atomicAdd(&ssum[c + 0], a.x);
    atomicAdd(&ssum[c + 1], a.y);
    atomicAdd(&ssum[c + 2], a.z);
    atomicAdd(&ssum[c + 3], a.w);
    atomicAdd(&ssq[c + 0], a.x * a.x);
    atomicAdd(&ssq[c + 1], a.y * a.y);
    atomicAdd(&ssq[c + 2], a.z * a.z);
    atomicAdd(&ssq[c + 3], a.w * a.w);
    __syncthreads();
    if (tid < HID) {
        asm volatile("red.global.add.f32 [%0], %1;" ::"l"(stats + tid), "f"(ssum[tid]) : "memory");
        asm volatile("red.global.add.f32 [%0], %1;" ::"l"(stats + HID + tid), "f"(ssq[tid]) : "memory");
    }
}

// ---------------- launch ----------------
extern "C" void kernel_launch(void* const* d_in, const int* in_sizes, int n_in,
                              void* d_out, int out_size) {
    const float* x = (const float*)d_in[0];
    const float* W_in = (const float*)d_in[1];
    const float* b_in = (const float*)d_in[2];
    const float* W_g = (const float*)d_in[3];
    const float* b_g = (const float*)d_in[4];
    const float* gamma = (const float*)d_in[5];
    const float* beta = (const float*)d_in[6];
    const float* W_out = (const float*)d_in[7];
    const float* b_out = (const float*)d_in[8];
    const void* ei = d_in[9];
    float* out = (float*)d_out;

    float *agg, *h0, *acc, *dis, *stats, *w;
    __half* t;
    uint32_t* wtf;
    int *cnt, *rowptr, *col, *blockoff;
    cudaGetSymbolAddress((void**)&t, g_t);
    cudaGetSymbolAddress((void**)&agg, g_agg);
    cudaGetSymbolAddress((void**)&h0, g_h0);
    cudaGetSymbolAddress((void**)&acc, g_acc);
    cudaGetSymbolAddress((void**)&dis, g_dis);
    cudaGetSymbolAddress((void**)&stats, g_stats);
    cudaGetSymbolAddress((void**)&wtf, g_wtf);
    cudaGetSymbolAddress((void**)&w, g_w);
    cudaGetSymbolAddress((void**)&cnt, g_cnt);
    cudaGetSymbolAddress((void**)&rowptr, g_rowptr);
    cudaGetSymbolAddress((void**)&col, g_col);
    cudaGetSymbolAddress((void**)&blockoff, g_blockoff);

    const int N = NNODES, E = NEDGES;

    // dyn smem: 2*ASLICE(2048) + Bs + scale/shift(256) words
    const int SH128 = (2 * 2048 + 8192 + 2 * HID) * 4;  // 50176
    const int SH64 = (2 * 2048 + 4096 + 2 * HID) * 4;   // 33792
    cudaFuncSetAttribute(gemm_tc<128, 0, 1, 0>, cudaFuncAttributeMaxDynamicSharedMemorySize, SH128);
    cudaFuncSetAttribute(gemm_tc<128, 0, 0, 1>, cudaFuncAttributeMaxDynamicSharedMemorySize, SH128);
    cudaFuncSetAttribute(gemm_tc<128, 1, 0, 1>, cudaFuncAttributeMaxDynamicSharedMemorySize, SH128);
    cudaFuncSetAttribute(gemm_tc<128, 2, 0, 1>, cudaFuncAttributeMaxDynamicSharedMemorySize, SH128);
    cudaFuncSetAttribute(gemm_tc<128, 3, 0, 1>, cudaFuncAttributeMaxDynamicSharedMemorySize, SH128);
    cudaFuncSetAttribute(gemm_tc<64, 4, 1, 0>, cudaFuncAttributeMaxDynamicSharedMemorySize, SH64);

    const int gb = (N + 127) / 128;  // 391
    const size_t WG = 8192;          // packed words per 128x128 matrix

    // GEMM0 kept at profiled launch index 3
    detect_kernel<<<1, 256>>>((const long long*)ei);                              // 0
    zero_all_kernel<<<(N + 255) / 256, 256>>>(cnt, stats);                        // 1
    wpack_kernel<<<(5 * 4096 + 2048 + 255) / 256, 256>>>(W_in, W_g, W_out, wtf);  // 2
    // 3 (PROFILED): h0 = x @ W_in + b_in  (h0 doubles as skip)
    gemm_tc<128, 0, 1, 0><<<gb, 256, SH128>>>(x, wtf, b_in, nullptr, nullptr, nullptr,
                                              nullptr, nullptr, h0, N);
    count_kernel<<<(E + 255) / 256, 256>>>(ei, cnt, E);                           // 4
    scan1_kernel<<<SCAN_NBLK, 256>>>(cnt, rowptr, blockoff, dis);                 // 5
    scan2_kernel<<<1, 256>>>(blockoff);                                           // 6
    scan3_kernel<<<SCAN_NBLK, 256>>>(rowptr, blockoff);                           // 7
    zero_all_kernel<<<(N + 255) / 256, 256>>>(cnt, stats);                        // 8
    scatter_kernel<<<(E + 255) / 256, 256>>>(ei, dis, rowptr, cnt, col, w, E);    // 9

    // t0 = h0 @ W_g[0]  (fp16 out)
    gemm_tc<128, 0, 0, 1><<<gb, 256, SH128>>>(h0, wtf + WG, nullptr, nullptr, nullptr,
                                              nullptr, nullptr, nullptr, t, N);
    agg_stats_kernel<<<N / 8, 256>>>(t, dis, rowptr, col, w, b_g, agg, stats);
    // h1 = relu(norm0(agg0)); acc = h1; t1 = h1 @ W_g[1]
    gemm_tc<128, 1, 0, 1><<<gb, 256, SH128>>>(agg, wtf + 2 * WG, nullptr, stats, gamma,
                                              beta, nullptr, acc, t, N);
    agg_stats_kernel<<<N / 8, 256>>>(t, dis, rowptr, col, w, b_g + HID, agg, stats + 256);
    // h2 = relu(norm1(agg1) + 0.5*h0); acc += h2; t2 = h2 @ W_g[2]
    gemm_tc<128, 2, 0, 1><<<gb, 256, SH128>>>(agg, wtf + 3 * WG, nullptr, stats + 256,
                                              gamma + HID, beta + HID, h0, acc, t, N);
    agg_stats_kernel<<<N / 8, 256>>>(t, dis, rowptr, col, w, b_g + 2 * HID, agg, stats + 512);
    // h3 = relu(norm2(agg2)); acc += h3; t3 = h3 @ W_g[3]
    gemm_tc<128, 3, 0, 1><<<gb, 256, SH128>>>(agg, wtf + 4 * WG, nullptr, stats + 512,
                                              gamma + 2 * HID, beta + 2 * HID, nullptr, acc, t, N);
    agg_stats_kernel<<<N / 8, 256>>>(t, dis, rowptr, col, w, b_g + 3 * HID, agg, stats + 768);
    // out = (acc + relu(norm3(agg3) + 0.5*h0)) @ W_out + b_out
    gemm_tc<64, 4, 1, 0><<<gb, 256, SH64>>>(agg, wtf + 5 * WG, b_out, stats + 768,
                                            gamma + 3 * HID, beta + 3 * HID, h0, acc, out, N);
}

// round 14
// speedup vs baseline: 1.8108x; 1.0284x over previous
#include <cuda_runtime.h>
#include <cuda_fp16.h>
#include <cstdint>

#define NNODES 50000
#define NEDGES 600000
#define HID 128
#define OUTC 64
#define NGCN 4
#define EPSBN 1e-5f
#define SKIPW 0.5f

#define SCAN_CHUNK 200
#define SCAN_NBLK 250  // 250*200 = 50000

// fp16 fragment-packed weights: 128-wide matrix = 8192 words, 64-wide = 4096
#define WTF_TOTAL (8192 * 5 + 4096)

// ---------------- scratch (static device globals; no runtime alloc) ----------------
__device__ __align__(16) __half g_t[NNODES * HID];    // t fp16
__device__ __align__(16) __half g_agg[NNODES * HID];  // agg fp16
__device__ __align__(16) __half g_h0[NNODES * HID];   // input-linear output == skip, fp16
__device__ float g_acc[NNODES * HID];                 // acc fp32 (RED target)
__device__ float g_dis[NNODES];
__device__ float g_stats[NGCN * 2 * HID];
__device__ __align__(16) uint32_t g_wtf[WTF_TOTAL];  // weights fp16, FRAGMENT-PACKED (m16n8k16)
__device__ int g_cnt[NNODES];
__device__ int g_rowptr[NNODES + 1];
__device__ int g_col[NEDGES];
__device__ float g_w[NEDGES];
__device__ int g_blockoff[SCAN_NBLK];
__device__ int g_is64;

// ---------------- detect edge dtype + zero cnt/stats (fused) ----------------
__global__ void detect_zero_kernel(const long long* __restrict__ ei64, int* cnt,
                                   float* stats) {
    int i = blockIdx.x * blockDim.x + threadIdx.x;
    if (i < NNODES) cnt[i] = 0;
    if (i < NGCN * 2 * HID) stats[i] = 0.0f;
    if (blockIdx.x == 0) {
        __shared__ int ok;
        if (threadIdx.x == 0) ok = 1;
        __syncthreads();
        for (int j = threadIdx.x; j < 4096; j += blockDim.x) {
            long long v = ei64[j];
            if (v < 0 || v >= NNODES) ok = 0;
        }
        __syncthreads();
        if (threadIdx.x == 0) g_is64 = ok;
    }
}

__device__ __forceinline__ int load_idx(const void* ei, int pos, int is64) {
    if (is64) return (int)((const long long*)ei)[pos];
    return ((const int*)ei)[pos];
}

// ---------------- pack all weights to fp16 in m16n8k16 B-fragment order ----------------
__device__ __forceinline__ void wpack_one(const float* __restrict__ src,
                                          uint32_t* __restrict__ dst, int BN, int r) {
    int lane = r & 31;
    int blk = r >> 5;
    int nb = blk % (BN / 8);
    int ks16 = blk / (BN / 8);
    int k0 = ks16 * 16 + (lane & 3) * 2;
    int n = nb * 8 + (lane >> 2);
    __half2 w0 = __floats2half2_rn(src[(size_t)k0 * BN + n], src[(size_t)(k0 + 1) * BN + n]);
    __half2 w1 = __floats2half2_rn(src[(size_t)(k0 + 8) * BN + n], src[(size_t)(k0 + 9) * BN + n]);
    dst[r * 2 + 0] = *(uint32_t*)&w0;
    dst[r * 2 + 1] = *(uint32_t*)&w1;
}

__global__ void wpack_kernel(const float* __restrict__ W_in, const float* __restrict__ W_g,
                             const float* __restrict__ W_out, uint32_t* __restrict__ wtf) {
    int idx = blockIdx.x * blockDim.x + threadIdx.x;
    if (idx < 5 * 4096) {
        int m = idx / 4096;
        int r = idx % 4096;
        const float* src = (m == 0) ? W_in : (W_g + (size_t)(m - 1) * HID * HID);
        wpack_one(src, wtf + (size_t)m * 8192, 128, r);
    } else if (idx < 5 * 4096 + 2048) {
        int r = idx - 5 * 4096;
        wpack_one(W_out, wtf + (size_t)5 * 8192, 64, r);
    }
}

// ---------------- CSR build ----------------
__global__ void count_kernel(const void* __restrict__ ei, int* cnt, int E) {
    int e = blockIdx.x * blockDim.x + threadIdx.x;
    if (e < E) atomicAdd(&cnt[load_idx(ei, E + e, g_is64)], 1);
}

// inclusive scan within chunk; also compute dis from cnt
__global__ void scan1_kernel(const int* __restrict__ cnt, int* rowptr, int* blockoff,
                             float* dis) {
    __shared__ int s[256];
    int b = blockIdx.x, t = threadIdx.x;
    int i = b * SCAN_CHUNK + t;
    int v = (t < SCAN_CHUNK) ? cnt[i] : 0;
    if (t < SCAN_CHUNK) dis[i] = rsqrtf((float)v + 1.0f);  // self-loop degree
    s[t] = v;
    __syncthreads();
#pragma unroll
    for (int d = 1; d < 256; d <<= 1) {
        int add = (t >= d) ? s[t - d] : 0;
        __syncthreads();
        s[t] += add;
        __syncthreads();
    }
    if (t < SCAN_CHUNK) rowptr[i + 1] = s[t];
    if (t == 255) blockoff[b] = s[SCAN_CHUNK - 1];
}

__global__ void scan2_kernel(int* blockoff) {
    __shared__ int s[256];
    int t = threadIdx.x;
    int v = (t < SCAN_NBLK) ? blockoff[t] : 0;
    s[t] = v;
    __syncthreads();
#pragma unroll
    for (int d = 1; d < 256; d <<= 1) {
        int add = (t >= d) ? s[t - d] : 0;
        __syncthreads();
        s[t] += add;
        __syncthreads();
    }
    if (t < SCAN_NBLK) blockoff[t] = s[t] - v;  // exclusive
}

// add block offsets; also re-zero cnt (scatter cursor)
__global__ void scan3_kernel(int* rowptr, const int* __restrict__ blockoff, int* cnt) {
    int b = blockIdx.x, t = threadIdx.x;
    int i = b * SCAN_CHUNK + t;
    if (t < SCAN_CHUNK) {
        rowptr[i + 1] += blockoff[b];
        cnt[i] = 0;
    }
    if (b == 0 && t == 0) rowptr[0] = 0;
}

__global__ void scatter_kernel(const void* __restrict__ ei, const float* __restrict__ dis,
                               const int* __restrict__ rowptr, int* cnt,
                               int* col, float* w, int E) {
    int e = blockIdx.x * blockDim.x + threadIdx.x;
    if (e >= E) return;
    int is64 = g_is64;
    int src = load_idx(ei, e, is64);
    int dst = load_idx(ei, E + e, is64);
    int p = rowptr[dst] + atomicAdd(&cnt[dst], 1);
    col[p] = src;
    w[p] = dis[src] * dis[dst];
}

// ---------------- FP16 tensor-core GEMM (m16n8k16, fp32 accumulate) ----------------
// C[M,BN] = f(A)[M,128] @ Wh[128,BN]   (Wh fp16 fragment-packed)
// AMODE 0: A plain
// AMODE 1: A = relu(agg*sc+sh);            acc  = A (init, fp32)
// AMODE 2: A = relu(agg*sc+sh + 0.5*skip); acc += A (red fp32)
// AMODE 3: A = relu(agg*sc+sh);            acc += A (red fp32)
// AMODE 4: A = accOld + relu(agg*sc+sh + 0.5*skip)   (output GEMM)
// EPI 1: C += bias.  OUTH 1: C stored as __half.  AF16 1: Ain (and skipb) are fp16.
#define MMA_F16(d, a0, a1, a2, a3, b0, b1)                                     \
    asm volatile(                                                              \
        "mma.sync.aligned.m16n8k16.row.col.f32.f16.f16.f32 "                   \
        "{%0,%1,%2,%3}, {%4,%5,%6,%7}, {%8,%9}, {%0,%1,%2,%3};"                \
        : "+f"((d)[0]), "+f"((d)[1]), "+f"((d)[2]), "+f"((d)[3])               \
        : "r"(a0), "r"(a1), "r"(a2), "r"(a3), "r"(b0), "r"(b1))

template <int BN, int AMODE, int EPI, int OUTH, int AF16>
__global__ __launch_bounds__(256, 2) void gemm_tc(
    const void* __restrict__ Ainv, const uint32_t* __restrict__ Wtf,
    const float* __restrict__ bias, const float* __restrict__ stats,
    const float* __restrict__ gamma, const float* __restrict__ beta,
    const __half* __restrict__ skipb, float* __restrict__ accb,
    void* __restrict__ Cv, int M) {
    constexpr int BM = 128, BK = 32;
    constexpr int NI = BN / 16;
    constexpr int NB8 = BN / 8;
    constexpr int ASLICE = 2048;  // 2 ks16 * 8 mb * 32 lanes * 4 slots (half2 words)
    constexpr int BSWORDS = 8 * NB8 * 32 * 2;  // whole W fp16-packed
    constexpr bool HASSKIP = (AMODE == 2 || AMODE == 4);

    extern __shared__ uint32_t smem[];
    uint32_t* As0 = smem;            // fragment-major A slice (ping)
    uint32_t* As1 = As0 + ASLICE;    // pong
    uint32_t* Bs = As1 + ASLICE;     // whole W, fragment-packed
    float* sscale = (float*)(Bs + BSWORDS);
    float* sshift = sscale + HID;

    const int tid = threadIdx.x;
    const int lane = tid & 31;
    const int wid = tid >> 5;
    const int row0 = blockIdx.x * BM;
    const int warp_m = (wid & 3) * 32;
    const int warp_n = (wid >> 2) * (BN / 2);
    const int mb0 = (wid & 3) * 2;   // m16-block index base
    const int nb0 = (wid >> 2) * NI; // n8-block index base

    if (AMODE != 0 && tid < HID) {
        float invN = 1.0f / (float)M;
        float mean = stats[tid] * invN;
        float var = stats[HID + tid] * invN - mean * mean;
        float sc = gamma[tid] * rsqrtf(var + EPSBN);
        sscale[tid] = sc;
        sshift[tid] = beta[tid] - mean * sc;
    }

    // stage whole fragment-packed W: straight uint4 copies
    for (int i = tid; i < BSWORDS / 4; i += 256)
        ((uint4*)Bs)[i] = ((const uint4*)Wtf)[i];

    float acc[2][NI][4];
#pragma unroll
    for (int mi = 0; mi < 2; mi++)
#pragma unroll
        for (int ni = 0; ni < NI; ni++)
#pragma unroll
            for (int j = 0; j < 4; j++) acc[mi][ni][j] = 0.0f;

    float4 pa[4], psk[4], pac[4];

    auto ldA = [&](int kb) {
#pragma unroll
        for (int u = 0; u < 4; u++) {
            int i = tid + u * 256;
            int r = i >> 3;
            int kc = (i & 7) * 4;
            int gr = row0 + r;
            size_t off = (size_t)gr * HID + kb * BK + kc;
            float4 z = make_float4(0.f, 0.f, 0.f, 0.f);
            if (AF16) {
                pa[u] = z;
                if (gr < M) {
                    uint2 u2 = *(const uint2*)((const __half*)Ainv + off);
                    float2 lo = __half22float2(*(__half2*)&u2.x);
                    float2 hi = __half22float2(*(__half2*)&u2.y);
                    pa[u] = make_float4(lo.x, lo.y, hi.x, hi.y);
                }
            } else {
                pa[u] = (gr < M) ? *(const float4*)((const float*)Ainv + off) : z;
            }
            if (HASSKIP) {
                psk[u] = z;
                if (gr < M) {
                    uint2 u2 = *(const uint2*)(skipb + off);
                    float2 lo = __half22float2(*(__half2*)&u2.x);
                    float2 hi = __half22float2(*(__half2*)&u2.y);
                    psk[u] = make_float4(lo.x, lo.y, hi.x, hi.y);
                }
            }
            if (AMODE == 4) pac[u] = (gr < M) ? *(const float4*)(accb + off) : z;
        }
    };

    // write v (4 consecutive cols) into m16n8k16 A-fragment positions as 2 half2 words
    auto storeA = [&](int kb, uint32_t* buf) {
#pragma unroll
        for (int u = 0; u < 4; u++) {
            int i = tid + u * 256;
            int r = i >> 3;
            int kc = (i & 7) * 4;  // 0,4,...,28
            int gr = row0 + r;
            int c = kb * BK + kc;
            float4 v = pa[u];
            if (AMODE != 0) {
                v.x = v.x * sscale[c + 0] + sshift[c + 0];
                v.y = v.y * sscale[c + 1] + sshift[c + 1];
                v.z = v.z * sscale[c + 2] + sshift[c + 2];
                v.w = v.w * sscale[c + 3] + sshift[c + 3];
                if (HASSKIP) {
                    v.x += SKIPW * psk[u].x;
                    v.y += SKIPW * psk[u].y;
                    v.z += SKIPW * psk[u].z;
                    v.w += SKIPW * psk[u].w;
                }
                v.x = fmaxf(v.x, 0.f);
                v.y = fmaxf(v.y, 0.f);
                v.z = fmaxf(v.z, 0.f);
                v.w = fmaxf(v.w, 0.f);
                if (AMODE == 1 && gr < M)
                    *(float4*)(accb + (size_t)gr * HID + c) = v;
                if ((AMODE == 2 || AMODE == 3) && gr < M)
                    asm volatile("red.global.add.v4.f32 [%0], {%1,%2,%3,%4};" ::
                                     "l"(accb + (size_t)gr * HID + c),
                                 "f"(v.x), "f"(v.y), "f"(v.z), "f"(v.w)
                                 : "memory");
                if (AMODE == 4) {
                    v.x += pac[u].x;
                    v.y += pac[u].y;
                    v.z += pac[u].z;
                    v.w += pac[u].w;
                }
            }
            int mb = r >> 4;
            int rm = r & 15;
            int ks = kc >> 4;     // 0 or 1 within BK=32 slice
            int kin = kc & 15;    // 0,4,8,12
            int lane0 = (rm & 7) * 4 + ((kin >> 1) & 3);
            int lane1 = (rm & 7) * 4 + (((kin >> 1) + 1) & 3);
            int slot = ((kin & 8) ? 2 : 0) + ((rm & 8) ? 1 : 0);
            uint32_t* base = buf + ((ks * 8 + mb) * 32) * 4;
            __half2 h0v = __floats2half2_rn(v.x, v.y);
            __half2 h1v = __floats2half2_rn(v.z, v.w);
            base[lane0 * 4 + slot] = *(uint32_t*)&h0v;
            base[lane1 * 4 + slot] = *(uint32_t*)&h1v;
        }
    };

    ldA(0);
    // sscale/sshift (tid<128) + Bs staging must be visible before storeA/MMA.
    __syncthreads();
    storeA(0, As0);
    __syncthreads();  // As0 visible to consumers

    for (int kb = 0; kb < HID / BK; kb++) {
        uint32_t* cur = (kb & 1) ? As1 : As0;
        uint32_t* nxt = (kb & 1) ? As0 : As1;
        if (kb < HID / BK - 1) ldA(kb + 1);  // LDG latency overlapped with MMAs
#pragma unroll
        for (int ks = 0; ks < 2; ks++) {  // two k16 steps per BK=32 slice
            uint4 af0 = *(const uint4*)(cur + ((ks * 8 + mb0) * 32 + lane) * 4);
            uint4 af1 = *(const uint4*)(cur + ((ks * 8 + mb0 + 1) * 32 + lane) * 4);
            const int ksg = kb * 2 + ks;  // global k16 index 0..7
            uint2 bf[NI];
#pragma unroll
            for (int ni = 0; ni < NI; ni++)
                bf[ni] = *(const uint2*)(Bs + ((ksg * NB8 + nb0 + ni) * 32 + lane) * 2);
#pragma unroll
            for (int ni = 0; ni < NI; ni++) {
                MMA_F16(acc[0][ni], af0.x, af0.y, af0.z, af0.w, bf[ni].x, bf[ni].y);
                MMA_F16(acc[1][ni], af1.x, af1.y, af1.z, af1.w, bf[ni].x, bf[ni].y);
            }
        }
        if (kb < HID / BK - 1) storeA(kb + 1, nxt);
        __syncthreads();
    }

#pragma unroll
    for (int mi = 0; mi < 2; mi++) {
        int rbase = row0 + warp_m + mi * 16 + (lane >> 2);
#pragma unroll
        for (int half = 0; half < 2; half++) {
            int r = rbase + half * 8;
            if (r >= M) continue;
#pragma unroll
            for (int ni = 0; ni < NI; ni++) {
                int c = warp_n + ni * 8 + (lane & 3) * 2;
                float v0 = acc[mi][ni][half * 2 + 0];
                float v1 = acc[mi][ni][half * 2 + 1];
                if (EPI) {
                    v0 += bias[c];
                    v1 += bias[c + 1];
                }
                if (OUTH) {
                    __half2 hv = __floats2half2_rn(v0, v1);
                    *(__half2*)((__half*)Cv + (size_t)r * BN + c) = hv;
                } else {
                    *(float2*)((float*)Cv + (size_t)r * BN + c) = make_float2(v0, v1);
                }
            }
        }
    }
}

// ---------------- CSR aggregation (fp16 t gather) + fused BN stats; agg stored fp16 ----------------
// one warp per dst row; lane covers cols lane*4..lane*4+3 (one uint2 = 4 halfs)
__global__ __launch_bounds__(256) void agg_stats_kernel(
    const __half* __restrict__ t, const float* __restrict__ dis,
    const int* __restrict__ rowptr, const int* __restrict__ col,
    const float* __restrict__ w, const float* __restrict__ bias,
    __half* __restrict__ agg, float* __restrict__ stats) {
    __shared__ float ssum[HID];
    __shared__ float ssq[HID];
    const int tid = threadIdx.x;
    const int lane = tid & 31;
    const int widx = tid >> 5;
    if (tid < HID) {
        ssum[tid] = 0.0f;
        ssq[tid] = 0.0f;
    }
    __syncthreads();

    const int row = blockIdx.x * 8 + widx;  // grid = NNODES/8
    const uint2* t2 = (const uint2*)t;      // 4 halfs per uint2; 32 uint2 per row

    auto load4 = [&](int r) -> float4 {
        uint2 u = __ldg(t2 + (size_t)r * 32 + lane);
        float2 lo = __half22float2(*(__half2*)&u.x);
        float2 hi = __half22float2(*(__half2*)&u.y);
        return make_float4(lo.x, lo.y, hi.x, hi.y);
    };

    float d = dis[row];
    float sn = d * d;
    float4 a = load4(row);
    a.x *= sn; a.y *= sn; a.z *= sn; a.w *= sn;

    const int e0 = rowptr[row];
    const int e1 = rowptr[row + 1];
    int e = e0;
    for (; e + 4 <= e1; e += 4) {
        int s0 = __ldg(col + e + 0), s1 = __ldg(col + e + 1);
        int s2 = __ldg(col + e + 2), s3 = __ldg(col + e + 3);
        float w0 = __ldg(w + e + 0), w1 = __ldg(w + e + 1);
        float w2 = __ldg(w + e + 2), w3 = __ldg(w + e + 3);
        float4 v0 = load4(s0);
        float4 v1 = load4(s1);
        float4 v2 = load4(s2);
        float4 v3 = load4(s3);
        a.x += v0.x * w0 + v1.x * w1 + v2.x * w2 + v3.x * w3;
        a.y += v0.y * w0 + v1.y * w1 + v2.y * w2 + v3.y * w3;
        a.z += v0.z * w0 + v1.z * w1 + v2.z * w2 + v3.z * w3;
        a.w += v0.w * w0 + v1.w * w1 + v2.w * w2 + v3.w * w3;
    }
    for (; e < e1; e++) {
        int s = __ldg(col + e);
        float wt = __ldg(w + e);
        float4 v = load4(s);
        a.x += v.x * wt;
        a.y += v.y * wt;
        a.z += v.z * wt;
        a.w += v.w * wt;
    }
    float4 b4 = *(const float4*)(bias + lane * 4);
    a.x += b4.x; a.y += b4.y; a.z += b4.z; a.w += b4.w;

    // store agg as fp16 (one uint2 per lane)
    {
        __half2 lo = __floats2half2_rn(a.x, a.y);
        __half2 hi = __floats2half2_rn(a.z, a.w);
        uint2 u;
        u.x = *(uint32_t*)&lo;
        u.y = *(uint32_t*)&hi;
        *((uint2*)agg + (size_t)row * 32 + lane) = u;
    }

    int c = lane * 4;
    atomicAdd(&ssum[c + 0], a.x);
    atomicAdd(&ssum[c + 1], a.y);
    atomicAdd(&ssum[c + 2], a.z);
    atomicAdd(&ssum[c + 3], a.w);
    atomicAdd(&ssq[c + 0], a.x * a.x);
    atomicAdd(&ssq[c + 1], a.y * a.y);
    atomicAdd(&ssq[c + 2], a.z * a.z);
    atomicAdd(&ssq[c + 3], a.w * a.w);
    __syncthreads();
    if (tid < HID) {
        asm volatile("red.global.add.f32 [%0], %1;" ::"l"(stats + tid), "f"(ssum[tid]) : "memory");
        asm volatile("red.global.add.f32 [%0], %1;" ::"l"(stats + HID + tid), "f"(ssq[tid]) : "memory");
    }
}

// ---------------- launch ----------------
extern "C" void kernel_launch(void* const* d_in, const int* in_sizes, int n_in,
                              void* d_out, int out_size) {
    const float* x = (const float*)d_in[0];
    const float* W_in = (const float*)d_in[1];
    const float* b_in = (const float*)d_in[2];
    const float* W_g = (const float*)d_in[3];
    const float* b_g = (const float*)d_in[4];
    const float* gamma = (const float*)d_in[5];
    const float* beta = (const float*)d_in[6];
    const float* W_out = (const float*)d_in[7];
    const float* b_out = (const float*)d_in[8];
    const void* ei = d_in[9];
    float* out = (float*)d_out;

    float *acc, *dis, *stats, *w;
    __half *t, *agg, *h0;
    uint32_t* wtf;
    int *cnt, *rowptr, *col, *blockoff;
    cudaGetSymbolAddress((void**)&t, g_t);
    cudaGetSymbolAddress((void**)&agg, g_agg);
    cudaGetSymbolAddress((void**)&h0, g_h0);
    cudaGetSymbolAddress((void**)&acc, g_acc);
    cudaGetSymbolAddress((void**)&dis, g_dis);
    cudaGetSymbolAddress((void**)&stats, g_stats);
    cudaGetSymbolAddress((void**)&wtf, g_wtf);
    cudaGetSymbolAddress((void**)&w, g_w);
    cudaGetSymbolAddress((void**)&cnt, g_cnt);
    cudaGetSymbolAddress((void**)&rowptr, g_rowptr);
    cudaGetSymbolAddress((void**)&col, g_col);
    cudaGetSymbolAddress((void**)&blockoff, g_blockoff);

    const int N = NNODES, E = NEDGES;

    // dyn smem: 2*ASLICE(2048) + Bs + scale/shift(256) words
    const int SH128 = (2 * 2048 + 8192 + 2 * HID) * 4;  // 50176
    const int SH64 = (2 * 2048 + 4096 + 2 * HID) * 4;   // 33792
    cudaFuncSetAttribute(gemm_tc<128, 0, 1, 1, 0>, cudaFuncAttributeMaxDynamicSharedMemorySize, SH128);
    cudaFuncSetAttribute(gemm_tc<128, 0, 0, 1, 1>, cudaFuncAttributeMaxDynamicSharedMemorySize, SH128);
    cudaFuncSetAttribute(gemm_tc<128, 1, 0, 1, 1>, cudaFuncAttributeMaxDynamicSharedMemorySize, SH128);
    cudaFuncSetAttribute(gemm_tc<128, 2, 0, 1, 1>, cudaFuncAttributeMaxDynamicSharedMemorySize, SH128);
    cudaFuncSetAttribute(gemm_tc<128, 3, 0, 1, 1>, cudaFuncAttributeMaxDynamicSharedMemorySize, SH128);
    cudaFuncSetAttribute(gemm_tc<64, 4, 1, 0, 1>, cudaFuncAttributeMaxDynamicSharedMemorySize, SH64);

    const int gb = (N + 127) / 128;  // 391
    const size_t WG = 8192;          // packed words per 128x128 matrix

    // GEMM0 kept at profiled launch index 3
    detect_zero_kernel<<<(N + 255) / 256, 256>>>((const long long*)ei, cnt, stats);   // 0
    wpack_kernel<<<(5 * 4096 + 2048 + 255) / 256, 256>>>(W_in, W_g, W_out, wtf);      // 1
    count_kernel<<<(E + 255) / 256, 256>>>(ei, cnt, E);                               // 2
    // 3 (PROFILED): h0 = x @ W_in + b_in  (fp16 out; doubles as skip)
    gemm_tc<128, 0, 1, 1, 0><<<gb, 256, SH128>>>(x, wtf, b_in, nullptr, nullptr, nullptr,
                                                 nullptr, nullptr, h0, N);
    scan1_kernel<<<SCAN_NBLK, 256>>>(cnt, rowptr, blockoff, dis);                     // 4
    scan2_kernel<<<1, 256>>>(blockoff);                                               // 5
    scan3_kernel<<<SCAN_NBLK, 256>>>(rowptr, blockoff, cnt);                          // 6
    scatter_kernel<<<(E + 255) / 256, 256>>>(ei, dis, rowptr, cnt, col, w, E);        // 7

    // t0 = h0 @ W_g[0]  (fp16 in, fp16 out)
    gemm_tc<128, 0, 0, 1, 1><<<gb, 256, SH128>>>(h0, wtf + WG, nullptr, nullptr, nullptr,
                                                 nullptr, nullptr, nullptr, t, N);
    agg_stats_kernel<<<N / 8, 256>>>(t, dis, rowptr, col, w, b_g, agg, stats);
    // h1 = relu(norm0(agg0)); acc = h1; t1 = h1 @ W_g[1]
    gemm_tc<128, 1, 0, 1, 1><<<gb, 256, SH128>>>(agg, wtf + 2 * WG, nullptr, stats, gamma,
                                                 beta, nullptr, acc, t, N);
    agg_stats_kernel<<<N / 8, 256>>>(t, dis, rowptr, col, w, b_g + HID, agg, stats + 256);
    // h2 = relu(norm1(agg1) + 0.5*h0); acc += h2; t2 = h2 @ W_g[2]
    gemm_tc<128, 2, 0, 1, 1><<<gb, 256, SH128>>>(agg, wtf + 3 * WG, nullptr, stats + 256,
                                                 gamma + HID, beta + HID, h0, acc, t, N);
    agg_stats_kernel<<<N / 8, 256>>>(t, dis, rowptr, col, w, b_g + 2 * HID, agg, stats + 512);
    // h3 = relu(norm2(agg2)); acc += h3; t3 = h3 @ W_g[3]
    gemm_tc<128, 3, 0, 1, 1><<<gb, 256, SH128>>>(agg, wtf + 4 * WG, nullptr, stats + 512,
                                                 gamma + 2 * HID, beta + 2 * HID, nullptr, acc, t, N);
    agg_stats_kernel<<<N / 8, 256>>>(t, dis, rowptr, col, w, b_g + 3 * HID, agg, stats + 768);
    // out = (acc + relu(norm3(agg3) + 0.5*h0)) @ W_out + b_out
    gemm_tc<64, 4, 1, 0, 1><<<gb, 256, SH64>>>(agg, wtf + 5 * WG, b_out, stats + 768,
                                               gamma + 3 * HID, beta + 3 * HID, h0, acc, out, N);
}

// round 15
// speedup vs baseline: 1.9141x; 1.0570x over previous
#include <cuda_runtime.h>
#include <cuda_fp16.h>
#include <cstdint>

#define NNODES 50000
#define NEDGES 600000
#define HID 128
#define OUTC 64
#define NGCN 4
#define EPSBN 1e-5f
#define SKIPW 0.5f

#define SCAN_CHUNK 200
#define SCAN_NBLK 250  // 250*200 = 50000

// fp16 fragment-packed weights: 128-wide matrix = 8192 words, 64-wide = 4096
#define WTF_TOTAL (8192 * 5 + 4096)

// ---------------- scratch (static device globals; no runtime alloc) ----------------
__device__ __align__(16) __half g_t[NNODES * HID];    // t fp16
__device__ __align__(16) __half g_agg[NNODES * HID];  // agg fp16
__device__ __align__(16) __half g_h0[NNODES * HID];   // input-linear output == skip, fp16
__device__ float g_acc[NNODES * HID];                 // acc fp32 (RED target)
__device__ float g_dis[NNODES];
__device__ float g_stats[NGCN * 2 * HID];
__device__ __align__(16) uint32_t g_wtf[WTF_TOTAL];  // weights fp16, FRAGMENT-PACKED (m16n8k16)
__device__ int g_cnt[NNODES];
__device__ int g_rowptr[NNODES + 1];
__device__ int g_col[NEDGES];
__device__ float g_w[NEDGES];
__device__ int g_blockoff[SCAN_NBLK];
__device__ int g_is64;

// ---------------- detect edge dtype + zero cnt/stats (fused) ----------------
__global__ void detect_zero_kernel(const long long* __restrict__ ei64, int* cnt,
                                   float* stats) {
    int i = blockIdx.x * blockDim.x + threadIdx.x;
    if (i < NNODES) cnt[i] = 0;
    if (i < NGCN * 2 * HID) stats[i] = 0.0f;
    if (blockIdx.x == 0) {
        __shared__ int ok;
        if (threadIdx.x == 0) ok = 1;
        __syncthreads();
        for (int j = threadIdx.x; j < 4096; j += blockDim.x) {
            long long v = ei64[j];
            if (v < 0 || v >= NNODES) ok = 0;
        }
        __syncthreads();
        if (threadIdx.x == 0) g_is64 = ok;
    }
}

__device__ __forceinline__ int load_idx(const void* ei, int pos, int is64) {
    if (is64) return (int)((const long long*)ei)[pos];
    return ((const int*)ei)[pos];
}

// ---------------- pack all weights to fp16 in m16n8k16 B-fragment order ----------------
__device__ __forceinline__ void wpack_one(const float* __restrict__ src,
                                          uint32_t* __restrict__ dst, int BN, int r) {
    int lane = r & 31;
    int blk = r >> 5;
    int nb = blk % (BN / 8);
    int ks16 = blk / (BN / 8);
    int k0 = ks16 * 16 + (lane & 3) * 2;
    int n = nb * 8 + (lane >> 2);
    __half2 w0 = __floats2half2_rn(src[(size_t)k0 * BN + n], src[(size_t)(k0 + 1) * BN + n]);
    __half2 w1 = __floats2half2_rn(src[(size_t)(k0 + 8) * BN + n], src[(size_t)(k0 + 9) * BN + n]);
    dst[r * 2 + 0] = *(uint32_t*)&w0;
    dst[r * 2 + 1] = *(uint32_t*)&w1;
}

__global__ void wpack_kernel(const float* __restrict__ W_in, const float* __restrict__ W_g,
                             const float* __restrict__ W_out, uint32_t* __restrict__ wtf) {
    int idx = blockIdx.x * blockDim.x + threadIdx.x;
    if (idx < 5 * 4096) {
        int m = idx / 4096;
        int r = idx % 4096;
        const float* src = (m == 0) ? W_in : (W_g + (size_t)(m - 1) * HID * HID);
        wpack_one(src, wtf + (size_t)m * 8192, 128, r);
    } else if (idx < 5 * 4096 + 2048) {
        int r = idx - 5 * 4096;
        wpack_one(W_out, wtf + (size_t)5 * 8192, 64, r);
    }
}

// ---------------- CSR build ----------------
__global__ void count_kernel(const void* __restrict__ ei, int* cnt, int E) {
    int e = blockIdx.x * blockDim.x + threadIdx.x;
    if (e < E) atomicAdd(&cnt[load_idx(ei, E + e, g_is64)], 1);
}

// inclusive scan within chunk; also compute dis from cnt
__global__ void scan1_kernel(const int* __restrict__ cnt, int* rowptr, int* blockoff,
                             float* dis) {
    __shared__ int s[256];
    int b = blockIdx.x, t = threadIdx.x;
    int i = b * SCAN_CHUNK + t;
    int v = (t < SCAN_CHUNK) ? cnt[i] : 0;
    if (t < SCAN_CHUNK) dis[i] = rsqrtf((float)v + 1.0f);  // self-loop degree
    s[t] = v;
    __syncthreads();
#pragma unroll
    for (int d = 1; d < 256; d <<= 1) {
        int add = (t >= d) ? s[t - d] : 0;
        __syncthreads();
        s[t] += add;
        __syncthreads();
    }
    if (t < SCAN_CHUNK) rowptr[i + 1] = s[t];
    if (t == 255) blockoff[b] = s[SCAN_CHUNK - 1];
}

__global__ void scan2_kernel(int* blockoff) {
    __shared__ int s[256];
    int t = threadIdx.x;
    int v = (t < SCAN_NBLK) ? blockoff[t] : 0;
    s[t] = v;
    __syncthreads();
#pragma unroll
    for (int d = 1; d < 256; d <<= 1) {
        int add = (t >= d) ? s[t - d] : 0;
        __syncthreads();
        s[t] += add;
        __syncthreads();
    }
    if (t < SCAN_NBLK) blockoff[t] = s[t] - v;  // exclusive
}

// add block offsets; also re-zero cnt (scatter cursor)
__global__ void scan3_kernel(int* rowptr, const int* __restrict__ blockoff, int* cnt) {
    int b = blockIdx.x, t = threadIdx.x;
    int i = b * SCAN_CHUNK + t;
    if (t < SCAN_CHUNK) {
        rowptr[i + 1] += blockoff[b];
        cnt[i] = 0;
    }
    if (b == 0 && t == 0) rowptr[0] = 0;
}

__global__ void scatter_kernel(const void* __restrict__ ei, const float* __restrict__ dis,
                               const int* __restrict__ rowptr, int* cnt,
                               int* col, float* w, int E) {
    int e = blockIdx.x * blockDim.x + threadIdx.x;
    if (e >= E) return;
    int is64 = g_is64;
    int src = load_idx(ei, e, is64);
    int dst = load_idx(ei, E + e, is64);
    int p = rowptr[dst] + atomicAdd(&cnt[dst], 1);
    col[p] = src;
    w[p] = dis[src] * dis[dst];
}

// ---------------- FP16 tensor-core GEMM (m16n8k16, fp32 accumulate), BM=64 ----------------
// C[M,BN] = f(A)[M,128] @ Wh[128,BN]   (Wh fp16 fragment-packed)
// 256 threads = 8 warps: 2 m-warps (32 rows each) x 4 n-groups (BN/4 cols each)
// AMODE 0: A plain
// AMODE 1: A = relu(agg*sc+sh);            acc  = A (init, fp32)
// AMODE 2: A = relu(agg*sc+sh + 0.5*skip); acc += A (red fp32)
// AMODE 3: A = relu(agg*sc+sh);            acc += A (red fp32)
// AMODE 4: A = accOld + relu(agg*sc+sh + 0.5*skip)   (output GEMM)
// EPI 1: C += bias.  OUTH 1: C stored as __half.  AF16 1: Ain (and skipb) are fp16.
#define MMA_F16(d, a0, a1, a2, a3, b0, b1)                                     \
    asm volatile(                                                              \
        "mma.sync.aligned.m16n8k16.row.col.f32.f16.f16.f32 "                   \
        "{%0,%1,%2,%3}, {%4,%5,%6,%7}, {%8,%9}, {%0,%1,%2,%3};"                \
        : "+f"((d)[0]), "+f"((d)[1]), "+f"((d)[2]), "+f"((d)[3])               \
        : "r"(a0), "r"(a1), "r"(a2), "r"(a3), "r"(b0), "r"(b1))

template <int BN, int AMODE, int EPI, int OUTH, int AF16>
__global__ __launch_bounds__(256) void gemm_tc(
    const void* __restrict__ Ainv, const uint32_t* __restrict__ Wtf,
    const float* __restrict__ bias, const float* __restrict__ stats,
    const float* __restrict__ gamma, const float* __restrict__ beta,
    const __half* __restrict__ skipb, float* __restrict__ accb,
    void* __restrict__ Cv, int M) {
    constexpr int BM = 64, BK = 32;
    constexpr int NI = BN / 32;                // n8-blocks per warp (4 for BN=128, 2 for BN=64)
    constexpr int NB8 = BN / 8;
    constexpr int ASLICE = 1024;               // 2 ks16 * 4 mb * 32 lanes * 4 slots
    constexpr int BSWORDS = 8 * NB8 * 32 * 2;  // whole W fp16-packed
    constexpr bool HASSKIP = (AMODE == 2 || AMODE == 4);

    extern __shared__ uint32_t smem[];
    uint32_t* As0 = smem;            // fragment-major A slice (ping)
    uint32_t* As1 = As0 + ASLICE;    // pong
    uint32_t* Bs = As1 + ASLICE;     // whole W, fragment-packed
    float* sscale = (float*)(Bs + BSWORDS);
    float* sshift = sscale + HID;

    const int tid = threadIdx.x;
    const int lane = tid & 31;
    const int wid = tid >> 5;
    const int row0 = blockIdx.x * BM;
    const int mwarp = wid & 1;                 // 0/1: which 32-row half
    const int ngrp = wid >> 1;                 // 0..3: which BN/4 column group
    const int warp_m = mwarp * 32;
    const int warp_n = ngrp * (BN / 4);
    const int mb0 = mwarp * 2;                 // m16-block base (0..3)
    const int nb0 = ngrp * NI;                 // n8-block base

    if (AMODE != 0 && tid < HID) {
        float invN = 1.0f / (float)M;
        float mean = stats[tid] * invN;
        float var = stats[HID + tid] * invN - mean * mean;
        float sc = gamma[tid] * rsqrtf(var + EPSBN);
        sscale[tid] = sc;
        sshift[tid] = beta[tid] - mean * sc;
    }

    // stage whole fragment-packed W: straight uint4 copies
    for (int i = tid; i < BSWORDS / 4; i += 256)
        ((uint4*)Bs)[i] = ((const uint4*)Wtf)[i];

    float acc[2][NI][4];
#pragma unroll
    for (int mi = 0; mi < 2; mi++)
#pragma unroll
        for (int ni = 0; ni < NI; ni++)
#pragma unroll
            for (int j = 0; j < 4; j++) acc[mi][ni][j] = 0.0f;

    float4 pa[2], psk[2], pac[2];

    auto ldA = [&](int kb) {
#pragma unroll
        for (int u = 0; u < 2; u++) {
            int i = tid + u * 256;
            int r = i >> 3;        // 0..63
            int kc = (i & 7) * 4;
            int gr = row0 + r;
            size_t off = (size_t)gr * HID + kb * BK + kc;
            float4 z = make_float4(0.f, 0.f, 0.f, 0.f);
            if (AF16) {
                pa[u] = z;
                if (gr < M) {
                    uint2 u2 = *(const uint2*)((const __half*)Ainv + off);
                    float2 lo = __half22float2(*(__half2*)&u2.x);
                    float2 hi = __half22float2(*(__half2*)&u2.y);
                    pa[u] = make_float4(lo.x, lo.y, hi.x, hi.y);
                }
            } else {
                pa[u] = (gr < M) ? *(const float4*)((const float*)Ainv + off) : z;
            }
            if (HASSKIP) {
                psk[u] = z;
                if (gr < M) {
                    uint2 u2 = *(const uint2*)(skipb + off);
                    float2 lo = __half22float2(*(__half2*)&u2.x);
                    float2 hi = __half22float2(*(__half2*)&u2.y);
                    psk[u] = make_float4(lo.x, lo.y, hi.x, hi.y);
                }
            }
            if (AMODE == 4) pac[u] = (gr < M) ? *(const float4*)(accb + off) : z;
        }
    };

    // write v (4 consecutive cols) into m16n8k16 A-fragment positions as 2 half2 words
    auto storeA = [&](int kb, uint32_t* buf) {
#pragma unroll
        for (int u = 0; u < 2; u++) {
            int i = tid + u * 256;
            int r = i >> 3;
            int kc = (i & 7) * 4;  // 0,4,...,28
            int gr = row0 + r;
            int c = kb * BK + kc;
            float4 v = pa[u];
            if (AMODE != 0) {
                v.x = v.x * sscale[c + 0] + sshift[c + 0];
                v.y = v.y * sscale[c + 1] + sshift[c + 1];
                v.z = v.z * sscale[c + 2] + sshift[c + 2];
                v.w = v.w * sscale[c + 3] + sshift[c + 3];
                if (HASSKIP) {
                    v.x += SKIPW * psk[u].x;
                    v.y += SKIPW * psk[u].y;
                    v.z += SKIPW * psk[u].z;
                    v.w += SKIPW * psk[u].w;
                }
                v.x = fmaxf(v.x, 0.f);
                v.y = fmaxf(v.y, 0.f);
                v.z = fmaxf(v.z, 0.f);
                v.w = fmaxf(v.w, 0.f);
                if (AMODE == 1 && gr < M)
                    *(float4*)(accb + (size_t)gr * HID + c) = v;
                if ((AMODE == 2 || AMODE == 3) && gr < M)
                    asm volatile("red.global.add.v4.f32 [%0], {%1,%2,%3,%4};" ::
                                     "l"(accb + (size_t)gr * HID + c),
                                 "f"(v.x), "f"(v.y), "f"(v.z), "f"(v.w)
                                 : "memory");
                if (AMODE == 4) {
                    v.x += pac[u].x;
                    v.y += pac[u].y;
                    v.z += pac[u].z;
                    v.w += pac[u].w;
                }
            }
            int mb = r >> 4;      // 0..3
            int rm = r & 15;
            int ks = kc >> 4;     // 0 or 1 within BK=32 slice
            int kin = kc & 15;    // 0,4,8,12
            int lane0 = (rm & 7) * 4 + ((kin >> 1) & 3);
            int lane1 = (rm & 7) * 4 + (((kin >> 1) + 1) & 3);
            int slot = ((kin & 8) ? 2 : 0) + ((rm & 8) ? 1 : 0);
            uint32_t* base = buf + ((ks * 4 + mb) * 32) * 4;
            __half2 h0v = __floats2half2_rn(v.x, v.y);
            __half2 h1v = __floats2half2_rn(v.z, v.w);
            base[lane0 * 4 + slot] = *(uint32_t*)&h0v;
            base[lane1 * 4 + slot] = *(uint32_t*)&h1v;
        }
    };

    ldA(0);
    // sscale/sshift (tid<128) + Bs staging must be visible before storeA/MMA.
    __syncthreads();
    storeA(0, As0);
    __syncthreads();  // As0 visible to consumers

    for (int kb = 0; kb < HID / BK; kb++) {
        uint32_t* cur = (kb & 1) ? As1 : As0;
        uint32_t* nxt = (kb & 1) ? As0 : As1;
        if (kb < HID / BK - 1) ldA(kb + 1);  // LDG latency overlapped with MMAs
#pragma unroll
        for (int ks = 0; ks < 2; ks++) {  // two k16 steps per BK=32 slice
            uint4 af0 = *(const uint4*)(cur + ((ks * 4 + mb0) * 32 + lane) * 4);
            uint4 af1 = *(const uint4*)(cur + ((ks * 4 + mb0 + 1) * 32 + lane) * 4);
            const int ksg = kb * 2 + ks;  // global k16 index 0..7
            uint2 bf[NI];
#pragma unroll
            for (int ni = 0; ni < NI; ni++)
                bf[ni] = *(const uint2*)(Bs + ((ksg * NB8 + nb0 + ni) * 32 + lane) * 2);
#pragma unroll
            for (int ni = 0; ni < NI; ni++) {
                MMA_F16(acc[0][ni], af0.x, af0.y, af0.z, af0.w, bf[ni].x, bf[ni].y);
                MMA_F16(acc[1][ni], af1.x, af1.y, af1.z, af1.w, bf[ni].x, bf[ni].y);
            }
        }
        if (kb < HID / BK - 1) storeA(kb + 1, nxt);
        __syncthreads();
    }

#pragma unroll
    for (int mi = 0; mi < 2; mi++) {
        int rbase = row0 + warp_m + mi * 16 + (lane >> 2);
#pragma unroll
        for (int half = 0; half < 2; half++) {
            int r = rbase + half * 8;
            if (r >= M) continue;
#pragma unroll
            for (int ni = 0; ni < NI; ni++) {
                int c = warp_n + ni * 8 + (lane & 3) * 2;
                float v0 = acc[mi][ni][half * 2 + 0];
                float v1 = acc[mi][ni][half * 2 + 1];
                if (EPI) {
                    v0 += bias[c];
                    v1 += bias[c + 1];
                }
                if (OUTH) {
                    __half2 hv = __floats2half2_rn(v0, v1);
                    *(__half2*)((__half*)Cv + (size_t)r * BN + c) = hv;
                } else {
                    *(float2*)((float*)Cv + (size_t)r * BN + c) = make_float2(v0, v1);
                }
            }
        }
    }
}

// ---------------- CSR aggregation (fp16 t gather) + fused BN stats; agg stored fp16 ----------------
// one warp per dst row; lane covers cols lane*4..lane*4+3 (one uint2 = 4 halfs)
__global__ __launch_bounds__(256) void agg_stats_kernel(
    const __half* __restrict__ t, const float* __restrict__ dis,
    const int* __restrict__ rowptr, const int* __restrict__ col,
    const float* __restrict__ w, const float* __restrict__ bias,
    __half* __restrict__ agg, float* __restrict__ stats) {
    __shared__ float ssum[HID];
    __shared__ float ssq[HID];
    const int tid = threadIdx.x;
    const int lane = tid & 31;
    const int widx = tid >> 5;
    if (tid < HID) {
        ssum[tid] = 0.0f;
        ssq[tid] = 0.0f;
    }
    __syncthreads();

    const int row = blockIdx.x * 8 + widx;  // grid = NNODES/8
    const uint2* t2 = (const uint2*)t;      // 4 halfs per uint2; 32 uint2 per row

    auto load4 = [&](int r) -> float4 {
        uint2 u = __ldg(t2 + (size_t)r * 32 + lane);
        float2 lo = __half22float2(*(__half2*)&u.x);
        float2 hi = __half22float2(*(__half2*)&u.y);
        return make_float4(lo.x, lo.y, hi.x, hi.y);
    };

    float d = dis[row];
    float sn = d * d;
    float4 a = load4(row);
    a.x *= sn; a.y *= sn; a.z *= sn; a.w *= sn;

    const int e0 = rowptr[row];
    const int e1 = rowptr[row + 1];
    int e = e0;
    for (; e + 4 <= e1; e += 4) {
        int s0 = __ldg(col + e + 0), s1 = __ldg(col + e + 1);
        int s2 = __ldg(col + e + 2), s3 = __ldg(col + e + 3);
        float w0 = __ldg(w + e + 0), w1 = __ldg(w + e + 1);
        float w2 = __ldg(w + e + 2), w3 = __ldg(w + e + 3);
        float4 v0 = load4(s0);
        float4 v1 = load4(s1);
        float4 v2 = load4(s2);
        float4 v3 = load4(s3);
        a.x += v0.x * w0 + v1.x * w1 + v2.x * w2 + v3.x * w3;
        a.y += v0.y * w0 + v1.y * w1 + v2.y * w2 + v3.y * w3;
        a.z += v0.z * w0 + v1.z * w1 + v2.z * w2 + v3.z * w3;
        a.w += v0.w * w0 + v1.w * w1 + v2.w * w2 + v3.w * w3;
    }
    for (; e < e1; e++) {
        int s = __ldg(col + e);
        float wt = __ldg(w + e);
        float4 v = load4(s);
        a.x += v.x * wt;
        a.y += v.y * wt;
        a.z += v.z * wt;
        a.w += v.w * wt;
    }
    float4 b4 = *(const float4*)(bias + lane * 4);
    a.x += b4.x; a.y += b4.y; a.z += b4.z; a.w += b4.w;

    // store agg as fp16 (one uint2 per lane)
    {
        __half2 lo = __floats2half2_rn(a.x, a.y);
        __half2 hi = __floats2half2_rn(a.z, a.w);
        uint2 u;
        u.x = *(uint32_t*)&lo;
        u.y = *(uint32_t*)&hi;
        *((uint2*)agg + (size_t)row * 32 + lane) = u;
    }

    int c = lane * 4;
    atomicAdd(&ssum[c + 0], a.x);
    atomicAdd(&ssum[c + 1], a.y);
    atomicAdd(&ssum[c + 2], a.z);
    atomicAdd(&ssum[c + 3], a.w);
    atomicAdd(&ssq[c + 0], a.x * a.x);
    atomicAdd(&ssq[c + 1], a.y * a.y);
    atomicAdd(&ssq[c + 2], a.z * a.z);
    atomicAdd(&ssq[c + 3], a.w * a.w);
    __syncthreads();
    if (tid < HID) {
        asm volatile("red.global.add.f32 [%0], %1;" ::"l"(stats + tid), "f"(ssum[tid]) : "memory");
        asm volatile("red.global.add.f32 [%0], %1;" ::"l"(stats + HID + tid), "f"(ssq[tid]) : "memory");
    }
}

// ---------------- launch ----------------
extern "C" void kernel_launch(void* const* d_in, const int* in_sizes, int n_in,
                              void* d_out, int out_size) {
    const float* x = (const float*)d_in[0];
    const float* W_in = (const float*)d_in[1];
    const float* b_in = (const float*)d_in[2];
    const float* W_g = (const float*)d_in[3];
    const float* b_g = (const float*)d_in[4];
    const float* gamma = (const float*)d_in[5];
    const float* beta = (const float*)d_in[6];
    const float* W_out = (const float*)d_in[7];
    const float* b_out = (const float*)d_in[8];
    const void* ei = d_in[9];
    float* out = (float*)d_out;

    float *acc, *dis, *stats, *w;
    __half *t, *agg, *h0;
    uint32_t* wtf;
    int *cnt, *rowptr, *col, *blockoff;
    cudaGetSymbolAddress((void**)&t, g_t);
    cudaGetSymbolAddress((void**)&agg, g_agg);
    cudaGetSymbolAddress((void**)&h0, g_h0);
    cudaGetSymbolAddress((void**)&acc, g_acc);
    cudaGetSymbolAddress((void**)&dis, g_dis);
    cudaGetSymbolAddress((void**)&stats, g_stats);
    cudaGetSymbolAddress((void**)&wtf, g_wtf);
    cudaGetSymbolAddress((void**)&w, g_w);
    cudaGetSymbolAddress((void**)&cnt, g_cnt);
    cudaGetSymbolAddress((void**)&rowptr, g_rowptr);
    cudaGetSymbolAddress((void**)&col, g_col);
    cudaGetSymbolAddress((void**)&blockoff, g_blockoff);

    const int N = NNODES, E = NEDGES;

    // dyn smem: 2*ASLICE(1024) + Bs + scale/shift(256) words
    const int SH128 = (2 * 1024 + 8192 + 2 * HID) * 4;  // 42 KB
    const int SH64 = (2 * 1024 + 4096 + 2 * HID) * 4;   // 26 KB
    cudaFuncSetAttribute(gemm_tc<128, 0, 1, 1, 0>, cudaFuncAttributeMaxDynamicSharedMemorySize, SH128);
    cudaFuncSetAttribute(gemm_tc<128, 0, 0, 1, 1>, cudaFuncAttributeMaxDynamicSharedMemorySize, SH128);
    cudaFuncSetAttribute(gemm_tc<128, 1, 0, 1, 1>, cudaFuncAttributeMaxDynamicSharedMemorySize, SH128);
    cudaFuncSetAttribute(gemm_tc<128, 2, 0, 1, 1>, cudaFuncAttributeMaxDynamicSharedMemorySize, SH128);
    cudaFuncSetAttribute(gemm_tc<128, 3, 0, 1, 1>, cudaFuncAttributeMaxDynamicSharedMemorySize, SH128);
    cudaFuncSetAttribute(gemm_tc<64, 4, 1, 0, 1>, cudaFuncAttributeMaxDynamicSharedMemorySize, SH64);

    const int gb = (N + 63) / 64;  // 782 (BM=64 tiles)
    const size_t WG = 8192;        // packed words per 128x128 matrix

    // GEMM0 kept at profiled launch index 3
    detect_zero_kernel<<<(N + 255) / 256, 256>>>((const long long*)ei, cnt, stats);   // 0
    wpack_kernel<<<(5 * 4096 + 2048 + 255) / 256, 256>>>(W_in, W_g, W_out, wtf);      // 1
    count_kernel<<<(E + 255) / 256, 256>>>(ei, cnt, E);                               // 2
    // 3 (PROFILED): h0 = x @ W_in + b_in  (fp16 out; doubles as skip)
    gemm_tc<128, 0, 1, 1, 0><<<gb, 256, SH128>>>(x, wtf, b_in, nullptr, nullptr, nullptr,
                                                 nullptr, nullptr, h0, N);
    scan1_kernel<<<SCAN_NBLK, 256>>>(cnt, rowptr, blockoff, dis);                     // 4
    scan2_kernel<<<1, 256>>>(blockoff);                                               // 5
    scan3_kernel<<<SCAN_NBLK, 256>>>(rowptr, blockoff, cnt);                          // 6
    scatter_kernel<<<(E + 255) / 256, 256>>>(ei, dis, rowptr, cnt, col, w, E);        // 7

    // t0 = h0 @ W_g[0]  (fp16 in, fp16 out)
    gemm_tc<128, 0, 0, 1, 1><<<gb, 256, SH128>>>(h0, wtf + WG, nullptr, nullptr, nullptr,
                                                 nullptr, nullptr, nullptr, t, N);
    agg_stats_kernel<<<N / 8, 256>>>(t, dis, rowptr, col, w, b_g, agg, stats);
    // h1 = relu(norm0(agg0)); acc = h1; t1 = h1 @ W_g[1]
    gemm_tc<128, 1, 0, 1, 1><<<gb, 256, SH128>>>(agg, wtf + 2 * WG, nullptr, stats, gamma,
                                                 beta, nullptr, acc, t, N);
    agg_stats_kernel<<<N / 8, 256>>>(t, dis, rowptr, col, w, b_g + HID, agg, stats + 256);
    // h2 = relu(norm1(agg1) + 0.5*h0); acc += h2; t2 = h2 @ W_g[2]
    gemm_tc<128, 2, 0, 1, 1><<<gb, 256, SH128>>>(agg, wtf + 3 * WG, nullptr, stats + 256,
                                                 gamma + HID, beta + HID, h0, acc, t, N);
    agg_stats_kernel<<<N / 8, 256>>>(t, dis, rowptr, col, w, b_g + 2 * HID, agg, stats + 512);
    // h3 = relu(norm2(agg2)); acc += h3; t3 = h3 @ W_g[3]
    gemm_tc<128, 3, 0, 1, 1><<<gb, 256, SH128>>>(agg, wtf + 4 * WG, nullptr, stats + 512,
                                                 gamma + 2 * HID, beta + 2 * HID, nullptr, acc, t, N);
    agg_stats_kernel<<<N / 8, 256>>>(t, dis, rowptr, col, w, b_g + 3 * HID, agg, stats + 768);
    // out = (acc + relu(norm3(agg3) + 0.5*h0)) @ W_out + b_out
    gemm_tc<64, 4, 1, 0, 1><<<gb, 256, SH64>>>(agg, wtf + 5 * WG, b_out, stats + 768,
                                               gamma + 3 * HID, beta + 3 * HID, h0, acc, out, N);
}

// round 16
// speedup vs baseline: 1.9565x; 1.0222x over previous
#include <cuda_runtime.h>
#include <cuda_fp16.h>
#include <cstdint>

#define NNODES 50000
#define NEDGES 600000
#define HID 128
#define OUTC 64
#define NGCN 4
#define EPSBN 1e-5f
#define SKIPW 0.5f

#define SCAN_CHUNK 200
#define SCAN_NBLK 250  // 250*200 = 50000

// fp16 fragment-packed weights: 128-wide matrix = 8192 words, 64-wide = 4096
#define WTF_TOTAL (8192 * 5 + 4096)

// ---------------- scratch (static device globals; no runtime alloc) ----------------
__device__ __align__(16) __half g_t[NNODES * HID];    // t fp16
__device__ __align__(16) __half g_agg[NNODES * HID];  // agg fp16
__device__ __align__(16) __half g_h0[NNODES * HID];   // input-linear output == skip, fp16
__device__ float g_acc[NNODES * HID];                 // acc fp32 (RED target)
__device__ float g_dis[NNODES];
__device__ float g_stats[NGCN * 2 * HID];
__device__ __align__(16) uint32_t g_wtf[WTF_TOTAL];  // weights fp16, FRAGMENT-PACKED (m16n8k16)
__device__ int g_cnt[NNODES];
__device__ int g_rowptr[NNODES + 1];
__device__ int g_col[NEDGES];
__device__ float g_w[NEDGES];
__device__ int g_blockoff[SCAN_NBLK];
__device__ int g_is64;

// ---------------- detect edge dtype + zero cnt/stats (fused) ----------------
__global__ void detect_zero_kernel(const long long* __restrict__ ei64, int* cnt,
                                   float* stats) {
    int i = blockIdx.x * blockDim.x + threadIdx.x;
    if (i < NNODES) cnt[i] = 0;
    if (i < NGCN * 2 * HID) stats[i] = 0.0f;
    if (blockIdx.x == 0) {
        __shared__ int ok;
        if (threadIdx.x == 0) ok = 1;
        __syncthreads();
        for (int j = threadIdx.x; j < 4096; j += blockDim.x) {
            long long v = ei64[j];
            if (v < 0 || v >= NNODES) ok = 0;
        }
        __syncthreads();
        if (threadIdx.x == 0) g_is64 = ok;
    }
}

__device__ __forceinline__ int load_idx(const void* ei, int pos, int is64) {
    if (is64) return (int)((const long long*)ei)[pos];
    return ((const int*)ei)[pos];
}

// ---------------- pack all weights to fp16 in m16n8k16 B-fragment order ----------------
__device__ __forceinline__ void wpack_one(const float* __restrict__ src,
                                          uint32_t* __restrict__ dst, int BN, int r) {
    int lane = r & 31;
    int blk = r >> 5;
    int nb = blk % (BN / 8);
    int ks16 = blk / (BN / 8);
    int k0 = ks16 * 16 + (lane & 3) * 2;
    int n = nb * 8 + (lane >> 2);
    __half2 w0 = __floats2half2_rn(src[(size_t)k0 * BN + n], src[(size_t)(k0 + 1) * BN + n]);
    __half2 w1 = __floats2half2_rn(src[(size_t)(k0 + 8) * BN + n], src[(size_t)(k0 + 9) * BN + n]);
    dst[r * 2 + 0] = *(uint32_t*)&w0;
    dst[r * 2 + 1] = *(uint32_t*)&w1;
}

__global__ void wpack_kernel(const float* __restrict__ W_in, const float* __restrict__ W_g,
                             const float* __restrict__ W_out, uint32_t* __restrict__ wtf) {
    int idx = blockIdx.x * blockDim.x + threadIdx.x;
    if (idx < 5 * 4096) {
        int m = idx / 4096;
        int r = idx % 4096;
        const float* src = (m == 0) ? W_in : (W_g + (size_t)(m - 1) * HID * HID);
        wpack_one(src, wtf + (size_t)m * 8192, 128, r);
    } else if (idx < 5 * 4096 + 2048) {
        int r = idx - 5 * 4096;
        wpack_one(W_out, wtf + (size_t)5 * 8192, 64, r);
    }
}

// ---------------- CSR build ----------------
__global__ void count_kernel(const void* __restrict__ ei, int* cnt, int E) {
    int e = blockIdx.x * blockDim.x + threadIdx.x;
    if (e < E) atomicAdd(&cnt[load_idx(ei, E + e, g_is64)], 1);
}

// inclusive scan within chunk; also compute dis from cnt
__global__ void scan1_kernel(const int* __restrict__ cnt, int* rowptr, int* blockoff,
                             float* dis) {
    __shared__ int s[256];
    int b = blockIdx.x, t = threadIdx.x;
    int i = b * SCAN_CHUNK + t;
    int v = (t < SCAN_CHUNK) ? cnt[i] : 0;
    if (t < SCAN_CHUNK) dis[i] = rsqrtf((float)v + 1.0f);  // self-loop degree
    s[t] = v;
    __syncthreads();
#pragma unroll
    for (int d = 1; d < 256; d <<= 1) {
        int add = (t >= d) ? s[t - d] : 0;
        __syncthreads();
        s[t] += add;
        __syncthreads();
    }
    if (t < SCAN_CHUNK) rowptr[i + 1] = s[t];
    if (t == 255) blockoff[b] = s[SCAN_CHUNK - 1];
}

// merged scan2+scan3: every block redundantly scans the 250 block totals,
// then adds its exclusive offset; also re-zeroes cnt (scatter cursor)
__global__ void scan3_kernel(int* rowptr, const int* __restrict__ blockoff, int* cnt) {
    __shared__ int s[256];
    int b = blockIdx.x, t = threadIdx.x;
    int v = (t < SCAN_NBLK) ? blockoff[t] : 0;
    s[t] = v;
    __syncthreads();
#pragma unroll
    for (int d = 1; d < 256; d <<= 1) {
        int add = (t >= d) ? s[t - d] : 0;
        __syncthreads();
        s[t] += add;
        __syncthreads();
    }
    int excl = (b == 0) ? 0 : s[b - 1];
    int i = b * SCAN_CHUNK + t;
    if (t < SCAN_CHUNK) {
        rowptr[i + 1] += excl;
        cnt[i] = 0;
    }
    if (b == 0 && t == 0) rowptr[0] = 0;
}

__global__ void scatter_kernel(const void* __restrict__ ei, const float* __restrict__ dis,
                               const int* __restrict__ rowptr, int* cnt,
                               int* col, float* w, int E) {
    int e = blockIdx.x * blockDim.x + threadIdx.x;
    if (e >= E) return;
    int is64 = g_is64;
    int src = load_idx(ei, e, is64);
    int dst = load_idx(ei, E + e, is64);
    int p = rowptr[dst] + atomicAdd(&cnt[dst], 1);
    col[p] = src;
    w[p] = dis[src] * dis[dst];
}

// ---------------- FP16 tensor-core GEMM (m16n8k16, fp32 acc), BM=64, PERSISTENT ----------------
// C[M,BN] = f(A)[M,128] @ Wh[128,BN]   (Wh fp16 fragment-packed)
// 256 threads = 8 warps: 2 m-warps x 4 n-groups. Each block loops over tiles
// (stride gridDim.x) keeping Bs staged once. A staged ROW-MAJOR (80B stride),
// consumed via ldmatrix.x4.
// AMODE 0: A plain
// AMODE 1: A = relu(agg*sc+sh);            acc  = A (init, fp32)
// AMODE 2: A = relu(agg*sc+sh + 0.5*skip); acc += A (red fp32)
// AMODE 3: A = relu(agg*sc+sh);            acc += A (red fp32)
// AMODE 4: A = accOld + relu(agg*sc+sh + 0.5*skip)   (output GEMM)
// EPI 1: C += bias.  OUTH 1: C stored as __half.  AF16 1: Ain (and skipb) are fp16.
#define MMA_F16(d, a0, a1, a2, a3, b0, b1)                                     \
    asm volatile(                                                              \
        "mma.sync.aligned.m16n8k16.row.col.f32.f16.f16.f32 "                   \
        "{%0,%1,%2,%3}, {%4,%5,%6,%7}, {%8,%9}, {%0,%1,%2,%3};"                \
        : "+f"((d)[0]), "+f"((d)[1]), "+f"((d)[2]), "+f"((d)[3])               \
        : "r"(a0), "r"(a1), "r"(a2), "r"(a3), "r"(b0), "r"(b1))

__device__ __forceinline__ void ldsm_x4(uint32_t& r0, uint32_t& r1, uint32_t& r2,
                                        uint32_t& r3, uint32_t saddr) {
    asm volatile("ldmatrix.sync.aligned.m8n8.x4.shared.b16 {%0,%1,%2,%3}, [%4];"
                 : "=r"(r0), "=r"(r1), "=r"(r2), "=r"(r3)
                 : "r"(saddr));
}

#define ASTRIDE 40  // halfs per A row (32 payload + 8 pad): 80B, conflict-free for LDSM

template <int BN, int AMODE, int EPI, int OUTH, int AF16>
__global__ __launch_bounds__(256, 3) void gemm_tc(
    const void* __restrict__ Ainv, const uint32_t* __restrict__ Wtf,
    const float* __restrict__ bias, const float* __restrict__ stats,
    const float* __restrict__ gamma, const float* __restrict__ beta,
    const __half* __restrict__ skipb, float* __restrict__ accb,
    void* __restrict__ Cv, int M, int ntiles) {
    constexpr int NI = BN / 32;   // n8-blocks per warp
    constexpr int NB8 = BN / 8;
    constexpr int AWORDS = 64 * ASTRIDE / 2;   // 1280 words per A buffer
    constexpr int BSWORDS = 8 * NB8 * 32 * 2;  // whole W fp16-packed
    constexpr bool HASSKIP = (AMODE == 2 || AMODE == 4);

    extern __shared__ uint32_t smem[];
    uint32_t* As0 = smem;           // row-major A slice (ping)
    uint32_t* As1 = As0 + AWORDS;   // pong
    uint32_t* Bs = As1 + AWORDS;    // whole W, fragment-packed
    float* sscale = (float*)(Bs + BSWORDS);
    float* sshift = sscale + HID;

    const int tid = threadIdx.x;
    const int lane = tid & 31;
    const int wid = tid >> 5;
    const int mwarp = wid & 1;
    const int ngrp = wid >> 1;
    const int warp_m = mwarp * 32;
    const int warp_n = ngrp * (BN / 4);
    const int nb0 = ngrp * NI;

    if (AMODE != 0 && tid < HID) {
        float invN = 1.0f / (float)M;
        float mean = stats[tid] * invN;
        float var = stats[HID + tid] * invN - mean * mean;
        float sc = gamma[tid] * rsqrtf(var + EPSBN);
        sscale[tid] = sc;
        sshift[tid] = beta[tid] - mean * sc;
    }

    // stage whole fragment-packed W once per block
    for (int i = tid; i < BSWORDS / 4; i += 256)
        ((uint4*)Bs)[i] = ((const uint4*)Wtf)[i];

    uint32_t asaddr[2];
    asaddr[0] = (uint32_t)__cvta_generic_to_shared(As0);
    asaddr[1] = (uint32_t)__cvta_generic_to_shared(As1);

    float4 pa[2], psk[2], pac[2];

    auto ldA = [&](int tile, int kb) {
#pragma unroll
        for (int u = 0; u < 2; u++) {
            int i = tid + u * 256;
            int r = i >> 3;        // 0..63
            int kc = (i & 7) * 4;
            int gr = tile * 64 + r;
            size_t off = (size_t)gr * HID + kb * 32 + kc;
            float4 z = make_float4(0.f, 0.f, 0.f, 0.f);
            if (AF16) {
                pa[u] = z;
                if (gr < M) {
                    uint2 u2 = *(const uint2*)((const __half*)Ainv + off);
                    float2 lo = __half22float2(*(__half2*)&u2.x);
                    float2 hi = __half22float2(*(__half2*)&u2.y);
                    pa[u] = make_float4(lo.x, lo.y, hi.x, hi.y);
                }
            } else {
                pa[u] = (gr < M) ? *(const float4*)((const float*)Ainv + off) : z;
            }
            if (HASSKIP) {
                psk[u] = z;
                if (gr < M) {
                    uint2 u2 = *(const uint2*)(skipb + off);
                    float2 lo = __half22float2(*(__half2*)&u2.x);
                    float2 hi = __half22float2(*(__half2*)&u2.y);
                    psk[u] = make_float4(lo.x, lo.y, hi.x, hi.y);
                }
            }
            if (AMODE == 4) pac[u] = (gr < M) ? *(const float4*)(accb + off) : z;
        }
    };

    // row-major store: 4 halfs (one STS.64) at As[r][kc]
    auto storeA = [&](int tile, int kb, uint32_t* buf) {
#pragma unroll
        for (int u = 0; u < 2; u++) {
            int i = tid + u * 256;
            int r = i >> 3;
            int kc = (i & 7) * 4;
            int gr = tile * 64 + r;
            int c = kb * 32 + kc;
            float4 v = pa[u];
            if (AMODE != 0) {
                v.x = v.x * sscale[c + 0] + sshift[c + 0];
                v.y = v.y * sscale[c + 1] + sshift[c + 1];
                v.z = v.z * sscale[c + 2] + sshift[c + 2];
                v.w = v.w * sscale[c + 3] + sshift[c + 3];
                if (HASSKIP) {
                    v.x += SKIPW * psk[u].x;
                    v.y += SKIPW * psk[u].y;
                    v.z += SKIPW * psk[u].z;
                    v.w += SKIPW * psk[u].w;
                }
                v.x = fmaxf(v.x, 0.f);
                v.y = fmaxf(v.y, 0.f);
                v.z = fmaxf(v.z, 0.f);
                v.w = fmaxf(v.w, 0.f);
                if (AMODE == 1 && gr < M)
                    *(float4*)(accb + (size_t)gr * HID + c) = v;
                if ((AMODE == 2 || AMODE == 3) && gr < M)
                    asm volatile("red.global.add.v4.f32 [%0], {%1,%2,%3,%4};" ::
                                     "l"(accb + (size_t)gr * HID + c),
                                 "f"(v.x), "f"(v.y), "f"(v.z), "f"(v.w)
                                 : "memory");
                if (AMODE == 4) {
                    v.x += pac[u].x;
                    v.y += pac[u].y;
                    v.z += pac[u].z;
                    v.w += pac[u].w;
                }
            }
            __half2 h0v = __floats2half2_rn(v.x, v.y);
            __half2 h1v = __floats2half2_rn(v.z, v.w);
            uint2 st;
            st.x = *(uint32_t*)&h0v;
            st.y = *(uint32_t*)&h1v;
            *(uint2*)((__half*)buf + r * ASTRIDE + kc) = st;
        }
    };

    const int tile0 = blockIdx.x;
    const bool active0 = (tile0 < ntiles);
    if (active0) ldA(tile0, 0);
    __syncthreads();  // sscale/sshift + Bs visible
    if (active0) storeA(tile0, 0, As0);
    __syncthreads();

    int buf = 0;
    for (int tile = tile0; tile < ntiles; tile += gridDim.x) {
        float acc[2][NI][4];
#pragma unroll
        for (int mi = 0; mi < 2; mi++)
#pragma unroll
            for (int ni = 0; ni < NI; ni++)
#pragma unroll
                for (int j = 0; j < 4; j++) acc[mi][ni][j] = 0.0f;

#pragma unroll
        for (int kb = 0; kb < 4; kb++) {
            int ntile = (kb < 3) ? tile : tile + (int)gridDim.x;
            int nkb = (kb < 3) ? kb + 1 : 0;
            bool hn = (ntile < ntiles);
            if (hn) ldA(ntile, nkb);  // LDG latency overlapped with MMAs
#pragma unroll
            for (int ks = 0; ks < 2; ks++) {
                uint32_t a[2][4];
#pragma unroll
                for (int mi = 0; mi < 2; mi++) {
                    int row = warp_m + mi * 16 + (lane & 15);
                    int colh = ks * 16 + ((lane >> 4) << 3);
                    uint32_t sa = asaddr[buf] + (uint32_t)(row * ASTRIDE + colh) * 2;
                    ldsm_x4(a[mi][0], a[mi][1], a[mi][2], a[mi][3], sa);
                }
                const int ksg = kb * 2 + ks;
                uint2 bf[NI];
#pragma unroll
                for (int ni = 0; ni < NI; ni++)
                    bf[ni] = *(const uint2*)(Bs + ((ksg * NB8 + nb0 + ni) * 32 + lane) * 2);
#pragma unroll
                for (int ni = 0; ni < NI; ni++) {
                    MMA_F16(acc[0][ni], a[0][0], a[0][1], a[0][2], a[0][3], bf[ni].x, bf[ni].y);
                    MMA_F16(acc[1][ni], a[1][0], a[1][1], a[1][2], a[1][3], bf[ni].x, bf[ni].y);
                }
            }
            if (hn) storeA(ntile, nkb, (buf ? As0 : As1));
            __syncthreads();
            buf ^= 1;
        }

        // epilogue for this tile
        const int row0 = tile * 64;
#pragma unroll
        for (int mi = 0; mi < 2; mi++) {
            int rbase = row0 + warp_m + mi * 16 + (lane >> 2);
#pragma unroll
            for (int half = 0; half < 2; half++) {
                int r = rbase + half * 8;
                if (r >= M) continue;
#pragma unroll
                for (int ni = 0; ni < NI; ni++) {
                    int c = warp_n + ni * 8 + (lane & 3) * 2;
                    float v0 = acc[mi][ni][half * 2 + 0];
                    float v1 = acc[mi][ni][half * 2 + 1];
                    if (EPI) {
                        v0 += bias[c];
                        v1 += bias[c + 1];
                    }
                    if (OUTH) {
                        __half2 hv = __floats2half2_rn(v0, v1);
                        *(__half2*)((__half*)Cv + (size_t)r * BN + c) = hv;
                    } else {
                        *(float2*)((float*)Cv + (size_t)r * BN + c) = make_float2(v0, v1);
                    }
                }
            }
        }
    }
}

// ---------------- CSR aggregation (fp16 t gather) + fused BN stats; agg stored fp16 ----------------
__global__ __launch_bounds__(256) void agg_stats_kernel(
    const __half* __restrict__ t, const float* __restrict__ dis,
    const int* __restrict__ rowptr, const int* __restrict__ col,
    const float* __restrict__ w, const float* __restrict__ bias,
    __half* __restrict__ agg, float* __restrict__ stats) {
    __shared__ float ssum[HID];
    __shared__ float ssq[HID];
    const int tid = threadIdx.x;
    const int lane = tid & 31;
    const int widx = tid >> 5;
    if (tid < HID) {
        ssum[tid] = 0.0f;
        ssq[tid] = 0.0f;
    }
    __syncthreads();

    const int row = blockIdx.x * 8 + widx;  // grid = NNODES/8
    const uint2* t2 = (const uint2*)t;

    auto load4 = [&](int r) -> float4 {
        uint2 u = __ldg(t2 + (size_t)r * 32 + lane);
        float2 lo = __half22float2(*(__half2*)&u.x);
        float2 hi = __half22float2(*(__half2*)&u.y);
        return make_float4(lo.x, lo.y, hi.x, hi.y);
    };

    float d = dis[row];
    float sn = d * d;
    float4 a = load4(row);
    a.x *= sn; a.y *= sn; a.z *= sn; a.w *= sn;

    const int e0 = rowptr[row];
    const int e1 = rowptr[row + 1];
    int e = e0;
    for (; e + 4 <= e1; e += 4) {
        int s0 = __ldg(col + e + 0), s1 = __ldg(col + e + 1);
        int s2 = __ldg(col + e + 2), s3 = __ldg(col + e + 3);
        float w0 = __ldg(w + e + 0), w1 = __ldg(w + e + 1);
        float w2 = __ldg(w + e + 2), w3 = __ldg(w + e + 3);
        float4 v0 = load4(s0);
        float4 v1 = load4(s1);
        float4 v2 = load4(s2);
        float4 v3 = load4(s3);
        a.x += v0.x * w0 + v1.x * w1 + v2.x * w2 + v3.x * w3;
        a.y += v0.y * w0 + v1.y * w1 + v2.y * w2 + v3.y * w3;
        a.z += v0.z * w0 + v1.z * w1 + v2.z * w2 + v3.z * w3;
        a.w += v0.w * w0 + v1.w * w1 + v2.w * w2 + v3.w * w3;
    }
    for (; e < e1; e++) {
        int s = __ldg(col + e);
        float wt = __ldg(w + e);
        float4 v = load4(s);
        a.x += v.x * wt;
        a.y += v.y * wt;
        a.z += v.z * wt;
        a.w += v.w * wt;
    }
    float4 b4 = *(const float4*)(bias + lane * 4);
    a.x += b4.x; a.y += b4.y; a.z += b4.z; a.w += b4.w;

    {
        __half2 lo = __floats2half2_rn(a.x, a.y);
        __half2 hi = __floats2half2_rn(a.z, a.w);
        uint2 u;
        u.x = *(uint32_t*)&lo;
        u.y = *(uint32_t*)&hi;
        *((uint2*)agg + (size_t)row * 32 + lane) = u;
    }

    int c = lane * 4;
    atomicAdd(&ssum[c + 0], a.x);
    atomicAdd(&ssum[c + 1], a.y);
    atomicAdd(&ssum[c + 2], a.z);
    atomicAdd(&ssum[c + 3], a.w);
    atomicAdd(&ssq[c + 0], a.x * a.x);
    atomicAdd(&ssq[c + 1], a.y * a.y);
    atomicAdd(&ssq[c + 2], a.z * a.z);
    atomicAdd(&ssq[c + 3], a.w * a.w);
    __syncthreads();
    if (tid < HID) {
        asm volatile("red.global.add.f32 [%0], %1;" ::"l"(stats + tid), "f"(ssum[tid]) : "memory");
        asm volatile("red.global.add.f32 [%0], %1;" ::"l"(stats + HID + tid), "f"(ssq[tid]) : "memory");
    }
}

// ---------------- launch ----------------
extern "C" void kernel_launch(void* const* d_in, const int* in_sizes, int n_in,
                              void* d_out, int out_size) {
    const float* x = (const float*)d_in[0];
    const float* W_in = (const float*)d_in[1];
    const float* b_in = (const float*)d_in[2];
    const float* W_g = (const float*)d_in[3];
    const float* b_g = (const float*)d_in[4];
    const float* gamma = (const float*)d_in[5];
    const float* beta = (const float*)d_in[6];
    const float* W_out = (const float*)d_in[7];
    const float* b_out = (const float*)d_in[8];
    const void* ei = d_in[9];
    float* out = (float*)d_out;

    float *acc, *dis, *stats, *w;
    __half *t, *agg, *h0;
    uint32_t* wtf;
    int *cnt, *rowptr, *col, *blockoff;
    cudaGetSymbolAddress((void**)&t, g_t);
    cudaGetSymbolAddress((void**)&agg, g_agg);
    cudaGetSymbolAddress((void**)&h0, g_h0);
    cudaGetSymbolAddress((void**)&acc, g_acc);
    cudaGetSymbolAddress((void**)&dis, g_dis);
    cudaGetSymbolAddress((void**)&stats, g_stats);
    cudaGetSymbolAddress((void**)&wtf, g_wtf);
    cudaGetSymbolAddress((void**)&w, g_w);
    cudaGetSymbolAddress((void**)&cnt, g_cnt);
    cudaGetSymbolAddress((void**)&rowptr, g_rowptr);
    cudaGetSymbolAddress((void**)&col, g_col);
    cudaGetSymbolAddress((void**)&blockoff, g_blockoff);

    const int N = NNODES, E = NEDGES;

    // dyn smem: 2*AWORDS(1280) + Bs + scale/shift(256) words
    const int SH128 = (2 * 1280 + 8192 + 2 * HID) * 4;  // 44032
    const int SH64 = (2 * 1280 + 4096 + 2 * HID) * 4;   // 27648
    cudaFuncSetAttribute(gemm_tc<128, 0, 1, 1, 0>, cudaFuncAttributeMaxDynamicSharedMemorySize, SH128);
    cudaFuncSetAttribute(gemm_tc<128, 0, 0, 1, 1>, cudaFuncAttributeMaxDynamicSharedMemorySize, SH128);
    cudaFuncSetAttribute(gemm_tc<128, 1, 0, 1, 1>, cudaFuncAttributeMaxDynamicSharedMemorySize, SH128);
    cudaFuncSetAttribute(gemm_tc<128, 2, 0, 1, 1>, cudaFuncAttributeMaxDynamicSharedMemorySize, SH128);
    cudaFuncSetAttribute(gemm_tc<128, 3, 0, 1, 1>, cudaFuncAttributeMaxDynamicSharedMemorySize, SH128);
    cudaFuncSetAttribute(gemm_tc<64, 4, 1, 0, 1>, cudaFuncAttributeMaxDynamicSharedMemorySize, SH64);

    const int ntiles = (N + 63) / 64;  // 782
    const int gb = 444;                // persistent: 3 blocks/SM x 148 SMs
    const size_t WG = 8192;            // packed words per 128x128 matrix

    // GEMM0 kept at profiled launch index 3
    detect_zero_kernel<<<(N + 255) / 256, 256>>>((const long long*)ei, cnt, stats);   // 0
    wpack_kernel<<<(5 * 4096 + 2048 + 255) / 256, 256>>>(W_in, W_g, W_out, wtf);      // 1
    count_kernel<<<(E + 255) / 256, 256>>>(ei, cnt, E);                               // 2
    // 3 (PROFILED): h0 = x @ W_in + b_in  (fp16 out; doubles as skip)
    gemm_tc<128, 0, 1, 1, 0><<<gb, 256, SH128>>>(x, wtf, b_in, nullptr, nullptr, nullptr,
                                                 nullptr, nullptr, h0, N, ntiles);
    scan1_kernel<<<SCAN_NBLK, 256>>>(cnt, rowptr, blockoff, dis);                     // 4
    scan3_kernel<<<SCAN_NBLK, 256>>>(rowptr, blockoff, cnt);                          // 5
    scatter_kernel<<<(E + 255) / 256, 256>>>(ei, dis, rowptr, cnt, col, w, E);        // 6

    // t0 = h0 @ W_g[0]  (fp16 in, fp16 out)
    gemm_tc<128, 0, 0, 1, 1><<<gb, 256, SH128>>>(h0, wtf + WG, nullptr, nullptr, nullptr,
                                                 nullptr, nullptr, nullptr, t, N, ntiles);
    agg_stats_kernel<<<N / 8, 256>>>(t, dis, rowptr, col, w, b_g, agg, stats);
    // h1 = relu(norm0(agg0)); acc = h1; t1 = h1 @ W_g[1]
    gemm_tc<128, 1, 0, 1, 1><<<gb, 256, SH128>>>(agg, wtf + 2 * WG, nullptr, stats, gamma,
                                                 beta, nullptr, acc, t, N, ntiles);
    agg_stats_kernel<<<N / 8, 256>>>(t, dis, rowptr, col, w, b_g + HID, agg, stats + 256);
    // h2 = relu(norm1(agg1) + 0.5*h0); acc += h2; t2 = h2 @ W_g[2]
    gemm_tc<128, 2, 0, 1, 1><<<gb, 256, SH128>>>(agg, wtf + 3 * WG, nullptr, stats + 256,
                                                 gamma + HID, beta + HID, h0, acc, t, N, ntiles);
    agg_stats_kernel<<<N / 8, 256>>>(t, dis, rowptr, col, w, b_g + 2 * HID, agg, stats + 512);
    // h3 = relu(norm2(agg2)); acc += h3; t3 = h3 @ W_g[3]
    gemm_tc<128, 3, 0, 1, 1><<<gb, 256, SH128>>>(agg, wtf + 4 * WG, nullptr, stats + 512,
                                                 gamma + 2 * HID, beta + 2 * HID, nullptr, acc, t, N, ntiles);
    agg_stats_kernel<<<N / 8, 256>>>(t, dis, rowptr, col, w, b_g + 3 * HID, agg, stats + 768);
    // out = (acc + relu(norm3(agg3) + 0.5*h0)) @ W_out + b_out
    gemm_tc<64, 4, 1, 0, 1><<<gb, 256, SH64>>>(agg, wtf + 5 * WG, b_out, stats + 768,
                                               gamma + 3 * HID, beta + 3 * HID, h0, acc, out, N, ntiles);
}

// round 17
// speedup vs baseline: 2.1389x; 1.0932x over previous
#include <cuda_runtime.h>
#include <cuda_fp16.h>
#include <cstdint>

#define NNODES 50000
#define NEDGES 600000
#define HID 128
#define OUTC 64
#define NGCN 4
#define EPSBN 1e-5f
#define SKIPW 0.5f

#define SCAN_CHUNK 200
#define SCAN_NBLK 250  // 250*200 = 50000

// fp16 fragment-packed weights: 128-wide matrix = 8192 words, 64-wide = 4096
#define WTF_TOTAL (8192 * 5 + 4096)

// ---------------- scratch (static device globals; no runtime alloc) ----------------
__device__ __align__(16) __half g_t[NNODES * HID];    // t fp16
__device__ __align__(16) __half g_agg[NNODES * HID];  // agg fp16
__device__ __align__(16) __half g_h0[NNODES * HID];   // input-linear output == skip, fp16
__device__ float g_acc[NNODES * HID];                 // acc fp32 (RED target)
__device__ float g_dis[NNODES];
__device__ float g_stats[NGCN * 2 * HID];
__device__ __align__(16) uint32_t g_wtf[WTF_TOTAL];  // weights fp16, FRAGMENT-PACKED (m16n8k16)
__device__ int g_cnt[NNODES];
__device__ int g_rowptr[NNODES + 1];
__device__ int g_col[NEDGES];
__device__ float g_w[NEDGES];
__device__ int g_blockoff[SCAN_NBLK];
__device__ int g_is64;

// ---------------- detect edge dtype + zero cnt/stats (fused) ----------------
__global__ void detect_zero_kernel(const long long* __restrict__ ei64, int* cnt,
                                   float* stats) {
    int i = blockIdx.x * blockDim.x + threadIdx.x;
    if (i < NNODES) cnt[i] = 0;
    if (i < NGCN * 2 * HID) stats[i] = 0.0f;
    if (blockIdx.x == 0) {
        __shared__ int ok;
        if (threadIdx.x == 0) ok = 1;
        __syncthreads();
        for (int j = threadIdx.x; j < 4096; j += blockDim.x) {
            long long v = ei64[j];
            if (v < 0 || v >= NNODES) ok = 0;
        }
        __syncthreads();
        if (threadIdx.x == 0) g_is64 = ok;
    }
}

__device__ __forceinline__ int load_idx(const void* ei, int pos, int is64) {
    if (is64) return (int)((const long long*)ei)[pos];
    return ((const int*)ei)[pos];
}

// ---------------- pack all weights to fp16 in m16n8k16 B-fragment order ----------------
__device__ __forceinline__ void wpack_one(const float* __restrict__ src,
                                          uint32_t* __restrict__ dst, int BN, int r) {
    int lane = r & 31;
    int blk = r >> 5;
    int nb = blk % (BN / 8);
    int ks16 = blk / (BN / 8);
    int k0 = ks16 * 16 + (lane & 3) * 2;
    int n = nb * 8 + (lane >> 2);
    __half2 w0 = __floats2half2_rn(src[(size_t)k0 * BN + n], src[(size_t)(k0 + 1) * BN + n]);
    __half2 w1 = __floats2half2_rn(src[(size_t)(k0 + 8) * BN + n], src[(size_t)(k0 + 9) * BN + n]);
    dst[r * 2 + 0] = *(uint32_t*)&w0;
    dst[r * 2 + 1] = *(uint32_t*)&w1;
}

__global__ void wpack_kernel(const float* __restrict__ W_in, const float* __restrict__ W_g,
                             const float* __restrict__ W_out, uint32_t* __restrict__ wtf) {
    int idx = blockIdx.x * blockDim.x + threadIdx.x;
    if (idx < 5 * 4096) {
        int m = idx / 4096;
        int r = idx % 4096;
        const float* src = (m == 0) ? W_in : (W_g + (size_t)(m - 1) * HID * HID);
        wpack_one(src, wtf + (size_t)m * 8192, 128, r);
    } else if (idx < 5 * 4096 + 2048) {
        int r = idx - 5 * 4096;
        wpack_one(W_out, wtf + (size_t)5 * 8192, 64, r);
    }
}

// ---------------- CSR build ----------------
__global__ void count_kernel(const void* __restrict__ ei, int* cnt, int E) {
    int e = blockIdx.x * blockDim.x + threadIdx.x;
    if (e < E) atomicAdd(&cnt[load_idx(ei, E + e, g_is64)], 1);
}

// inclusive scan within chunk; also compute dis from cnt
__global__ void scan1_kernel(const int* __restrict__ cnt, int* rowptr, int* blockoff,
                             float* dis) {
    __shared__ int s[256];
    int b = blockIdx.x, t = threadIdx.x;
    int i = b * SCAN_CHUNK + t;
    int v = (t < SCAN_CHUNK) ? cnt[i] : 0;
    if (t < SCAN_CHUNK) dis[i] = rsqrtf((float)v + 1.0f);  // self-loop degree
    s[t] = v;
    __syncthreads();
#pragma unroll
    for (int d = 1; d < 256; d <<= 1) {
        int add = (t >= d) ? s[t - d] : 0;
        __syncthreads();
        s[t] += add;
        __syncthreads();
    }
    if (t < SCAN_CHUNK) rowptr[i + 1] = s[t];
    if (t == 255) blockoff[b] = s[SCAN_CHUNK - 1];
}

// merged scan2+scan3: every block redundantly scans the 250 block totals,
// then adds its exclusive offset; also re-zeroes cnt (scatter cursor)
__global__ void scan3_kernel(int* rowptr, const int* __restrict__ blockoff, int* cnt) {
    __shared__ int s[256];
    int b = blockIdx.x, t = threadIdx.x;
    int v = (t < SCAN_NBLK) ? blockoff[t] : 0;
    s[t] = v;
    __syncthreads();
#pragma unroll
    for (int d = 1; d < 256; d <<= 1) {
        int add = (t >= d) ? s[t - d] : 0;
        __syncthreads();
        s[t] += add;
        __syncthreads();
    }
    int excl = (b == 0) ? 0 : s[b - 1];
    int i = b * SCAN_CHUNK + t;
    if (t < SCAN_CHUNK) {
        rowptr[i + 1] += excl;
        cnt[i] = 0;
    }
    if (b == 0 && t == 0) rowptr[0] = 0;
}

__global__ void scatter_kernel(const void* __restrict__ ei, const float* __restrict__ dis,
                               const int* __restrict__ rowptr, int* cnt,
                               int* col, float* w, int E) {
    int e = blockIdx.x * blockDim.x + threadIdx.x;
    if (e >= E) return;
    int is64 = g_is64;
    int src = load_idx(ei, e, is64);
    int dst = load_idx(ei, E + e, is64);
    int p = rowptr[dst] + atomicAdd(&cnt[dst], 1);
    col[p] = src;
    w[p] = dis[src] * dis[dst];
}

// ---------------- FP16 tensor-core GEMM (m16n8k16, fp32 acc), BM=64, PERSISTENT ----------------
// (unchanged from round 15)
#define MMA_F16(d, a0, a1, a2, a3, b0, b1)                                     \
    asm volatile(                                                              \
        "mma.sync.aligned.m16n8k16.row.col.f32.f16.f16.f32 "                   \
        "{%0,%1,%2,%3}, {%4,%5,%6,%7}, {%8,%9}, {%0,%1,%2,%3};"                \
        : "+f"((d)[0]), "+f"((d)[1]), "+f"((d)[2]), "+f"((d)[3])               \
        : "r"(a0), "r"(a1), "r"(a2), "r"(a3), "r"(b0), "r"(b1))

__device__ __forceinline__ void ldsm_x4(uint32_t& r0, uint32_t& r1, uint32_t& r2,
                                        uint32_t& r3, uint32_t saddr) {
    asm volatile("ldmatrix.sync.aligned.m8n8.x4.shared.b16 {%0,%1,%2,%3}, [%4];"
                 : "=r"(r0), "=r"(r1), "=r"(r2), "=r"(r3)
                 : "r"(saddr));
}

#define ASTRIDE 40  // halfs per A row (32 payload + 8 pad): 80B, conflict-free for LDSM

template <int BN, int AMODE, int EPI, int OUTH, int AF16>
__global__ __launch_bounds__(256, 3) void gemm_tc(
    const void* __restrict__ Ainv, const uint32_t* __restrict__ Wtf,
    const float* __restrict__ bias, const float* __restrict__ stats,
    const float* __restrict__ gamma, const float* __restrict__ beta,
    const __half* __restrict__ skipb, float* __restrict__ accb,
    void* __restrict__ Cv, int M, int ntiles) {
    constexpr int NI = BN / 32;   // n8-blocks per warp
    constexpr int NB8 = BN / 8;
    constexpr int AWORDS = 64 * ASTRIDE / 2;   // 1280 words per A buffer
    constexpr int BSWORDS = 8 * NB8 * 32 * 2;  // whole W fp16-packed
    constexpr bool HASSKIP = (AMODE == 2 || AMODE == 4);

    extern __shared__ uint32_t smem[];
    uint32_t* As0 = smem;           // row-major A slice (ping)
    uint32_t* As1 = As0 + AWORDS;   // pong
    uint32_t* Bs = As1 + AWORDS;    // whole W, fragment-packed
    float* sscale = (float*)(Bs + BSWORDS);
    float* sshift = sscale + HID;

    const int tid = threadIdx.x;
    const int lane = tid & 31;
    const int wid = tid >> 5;
    const int mwarp = wid & 1;
    const int ngrp = wid >> 1;
    const int warp_m = mwarp * 32;
    const int warp_n = ngrp * (BN / 4);
    const int nb0 = ngrp * NI;

    if (AMODE != 0 && tid < HID) {
        float invN = 1.0f / (float)M;
        float mean = stats[tid] * invN;
        float var = stats[HID + tid] * invN - mean * mean;
        float sc = gamma[tid] * rsqrtf(var + EPSBN);
        sscale[tid] = sc;
        sshift[tid] = beta[tid] - mean * sc;
    }

    // stage whole fragment-packed W once per block
    for (int i = tid; i < BSWORDS / 4; i += 256)
        ((uint4*)Bs)[i] = ((const uint4*)Wtf)[i];

    uint32_t asaddr[2];
    asaddr[0] = (uint32_t)__cvta_generic_to_shared(As0);
    asaddr[1] = (uint32_t)__cvta_generic_to_shared(As1);

    float4 pa[2], psk[2], pac[2];

    auto ldA = [&](int tile, int kb) {
#pragma unroll
        for (int u = 0; u < 2; u++) {
            int i = tid + u * 256;
            int r = i >> 3;        // 0..63
            int kc = (i & 7) * 4;
            int gr = tile * 64 + r;
            size_t off = (size_t)gr * HID + kb * 32 + kc;
            float4 z = make_float4(0.f, 0.f, 0.f, 0.f);
            if (AF16) {
                pa[u] = z;
                if (gr < M) {
                    uint2 u2 = *(const uint2*)((const __half*)Ainv + off);
                    float2 lo = __half22float2(*(__half2*)&u2.x);
                    float2 hi = __half22float2(*(__half2*)&u2.y);
                    pa[u] = make_float4(lo.x, lo.y, hi.x, hi.y);
                }
            } else {
                pa[u] = (gr < M) ? *(const float4*)((const float*)Ainv + off) : z;
            }
            if (HASSKIP) {
                psk[u] = z;
                if (gr < M) {
                    uint2 u2 = *(const uint2*)(skipb + off);
                    float2 lo = __half22float2(*(__half2*)&u2.x);
                    float2 hi = __half22float2(*(__half2*)&u2.y);
                    psk[u] = make_float4(lo.x, lo.y, hi.x, hi.y);
                }
            }
            if (AMODE == 4) pac[u] = (gr < M) ? *(const float4*)(accb + off) : z;
        }
    };

    // row-major store: 4 halfs (one STS.64) at As[r][kc]
    auto storeA = [&](int tile, int kb, uint32_t* buf) {
#pragma unroll
        for (int u = 0; u < 2; u++) {
            int i = tid + u * 256;
            int r = i >> 3;
            int kc = (i & 7) * 4;
            int gr = tile * 64 + r;
            int c = kb * 32 + kc;
            float4 v = pa[u];
            if (AMODE != 0) {
                v.x = v.x * sscale[c + 0] + sshift[c + 0];
                v.y = v.y * sscale[c + 1] + sshift[c + 1];
                v.z = v.z * sscale[c + 2] + sshift[c + 2];
                v.w = v.w * sscale[c + 3] + sshift[c + 3];
                if (HASSKIP) {
                    v.x += SKIPW * psk[u].x;
                    v.y += SKIPW * psk[u].y;
                    v.z += SKIPW * psk[u].z;
                    v.w += SKIPW * psk[u].w;
                }
                v.x = fmaxf(v.x, 0.f);
                v.y = fmaxf(v.y, 0.f);
                v.z = fmaxf(v.z, 0.f);
                v.w = fmaxf(v.w, 0.f);
                if (AMODE == 1 && gr < M)
                    *(float4*)(accb + (size_t)gr * HID + c) = v;
                if ((AMODE == 2 || AMODE == 3) && gr < M)
                    asm volatile("red.global.add.v4.f32 [%0], {%1,%2,%3,%4};" ::
                                     "l"(accb + (size_t)gr * HID + c),
                                 "f"(v.x), "f"(v.y), "f"(v.z), "f"(v.w)
                                 : "memory");
                if (AMODE == 4) {
                    v.x += pac[u].x;
                    v.y += pac[u].y;
                    v.z += pac[u].z;
                    v.w += pac[u].w;
                }
            }
            __half2 h0v = __floats2half2_rn(v.x, v.y);
            __half2 h1v = __floats2half2_rn(v.z, v.w);
            uint2 st;
            st.x = *(uint32_t*)&h0v;
            st.y = *(uint32_t*)&h1v;
            *(uint2*)((__half*)buf + r * ASTRIDE + kc) = st;
        }
    };

    const int tile0 = blockIdx.x;
    const bool active0 = (tile0 < ntiles);
    if (active0) ldA(tile0, 0);
    __syncthreads();  // sscale/sshift + Bs visible
    if (active0) storeA(tile0, 0, As0);
    __syncthreads();

    int buf = 0;
    for (int tile = tile0; tile < ntiles; tile += gridDim.x) {
        float acc[2][NI][4];
#pragma unroll
        for (int mi = 0; mi < 2; mi++)
#pragma unroll
            for (int ni = 0; ni < NI; ni++)
#pragma unroll
                for (int j = 0; j < 4; j++) acc[mi][ni][j] = 0.0f;

#pragma unroll
        for (int kb = 0; kb < 4; kb++) {
            int ntile = (kb < 3) ? tile : tile + (int)gridDim.x;
            int nkb = (kb < 3) ? kb + 1 : 0;
            bool hn = (ntile < ntiles);
            if (hn) ldA(ntile, nkb);  // LDG latency overlapped with MMAs
#pragma unroll
            for (int ks = 0; ks < 2; ks++) {
                uint32_t a[2][4];
#pragma unroll
                for (int mi = 0; mi < 2; mi++) {
                    int row = warp_m + mi * 16 + (lane & 15);
                    int colh = ks * 16 + ((lane >> 4) << 3);
                    uint32_t sa = asaddr[buf] + (uint32_t)(row * ASTRIDE + colh) * 2;
                    ldsm_x4(a[mi][0], a[mi][1], a[mi][2], a[mi][3], sa);
                }
                const int ksg = kb * 2 + ks;
                uint2 bf[NI];
#pragma unroll
                for (int ni = 0; ni < NI; ni++)
                    bf[ni] = *(const uint2*)(Bs + ((ksg * NB8 + nb0 + ni) * 32 + lane) * 2);
#pragma unroll
                for (int ni = 0; ni < NI; ni++) {
                    MMA_F16(acc[0][ni], a[0][0], a[0][1], a[0][2], a[0][3], bf[ni].x, bf[ni].y);
                    MMA_F16(acc[1][ni], a[1][0], a[1][1], a[1][2], a[1][3], bf[ni].x, bf[ni].y);
                }
            }
            if (hn) storeA(ntile, nkb, (buf ? As0 : As1));
            __syncthreads();
            buf ^= 1;
        }

        // epilogue for this tile
        const int row0 = tile * 64;
#pragma unroll
        for (int mi = 0; mi < 2; mi++) {
            int rbase = row0 + warp_m + mi * 16 + (lane >> 2);
#pragma unroll
            for (int half = 0; half < 2; half++) {
                int r = rbase + half * 8;
                if (r >= M) continue;
#pragma unroll
                for (int ni = 0; ni < NI; ni++) {
                    int c = warp_n + ni * 8 + (lane & 3) * 2;
                    float v0 = acc[mi][ni][half * 2 + 0];
                    float v1 = acc[mi][ni][half * 2 + 1];
                    if (EPI) {
                        v0 += bias[c];
                        v1 += bias[c + 1];
                    }
                    if (OUTH) {
                        __half2 hv = __floats2half2_rn(v0, v1);
                        *(__half2*)((__half*)Cv + (size_t)r * BN + c) = hv;
                    } else {
                        *(float2*)((float*)Cv + (size_t)r * BN + c) = make_float2(v0, v1);
                    }
                }
            }
        }
    }
}

// ---------------- CSR aggregation (fp16 t gather, MLP=8) + BN stats (no shared atomics) ----------------
// one warp per dst row; lane covers cols lane*4..lane*4+3 (one uint2 = 4 halfs)
// stats: per-warp plain STS into padded [8][HID+4] buffers, then 8-way LDS reduce.
__global__ __launch_bounds__(256) void agg_stats_kernel(
    const __half* __restrict__ t, const float* __restrict__ dis,
    const int* __restrict__ rowptr, const int* __restrict__ col,
    const float* __restrict__ w, const float* __restrict__ bias,
    __half* __restrict__ agg, float* __restrict__ stats) {
    __shared__ float ssum[8][HID + 4];
    __shared__ float ssq[8][HID + 4];
    const int tid = threadIdx.x;
    const int lane = tid & 31;
    const int widx = tid >> 5;

    const int row = blockIdx.x * 8 + widx;  // grid = NNODES/8
    const uint2* t2 = (const uint2*)t;

    auto load4 = [&](int r) -> float4 {
        uint2 u = __ldg(t2 + (size_t)r * 32 + lane);
        float2 lo = __half22float2(*(__half2*)&u.x);
        float2 hi = __half22float2(*(__half2*)&u.y);
        return make_float4(lo.x, lo.y, hi.x, hi.y);
    };

    float d = dis[row];
    float sn = d * d;
    float4 a = load4(row);
    a.x *= sn; a.y *= sn; a.z *= sn; a.w *= sn;

    const int e0 = rowptr[row];
    const int e1 = rowptr[row + 1];
    int e = e0;
    // 8 independent gathers in flight
    for (; e + 8 <= e1; e += 8) {
        int s[8];
        float wt[8];
#pragma unroll
        for (int j = 0; j < 8; j++) {
            s[j] = __ldg(col + e + j);
            wt[j] = __ldg(w + e + j);
        }
        float4 v[8];
#pragma unroll
        for (int j = 0; j < 8; j++) v[j] = load4(s[j]);
#pragma unroll
        for (int j = 0; j < 8; j++) {
            a.x += v[j].x * wt[j];
            a.y += v[j].y * wt[j];
            a.z += v[j].z * wt[j];
            a.w += v[j].w * wt[j];
        }
    }
    for (; e + 4 <= e1; e += 4) {
        int s0 = __ldg(col + e + 0), s1 = __ldg(col + e + 1);
        int s2 = __ldg(col + e + 2), s3 = __ldg(col + e + 3);
        float w0 = __ldg(w + e + 0), w1 = __ldg(w + e + 1);
        float w2 = __ldg(w + e + 2), w3 = __ldg(w + e + 3);
        float4 v0 = load4(s0);
        float4 v1 = load4(s1);
        float4 v2 = load4(s2);
        float4 v3 = load4(s3);
        a.x += v0.x * w0 + v1.x * w1 + v2.x * w2 + v3.x * w3;
        a.y += v0.y * w0 + v1.y * w1 + v2.y * w2 + v3.y * w3;
        a.z += v0.z * w0 + v1.z * w1 + v2.z * w2 + v3.z * w3;
        a.w += v0.w * w0 + v1.w * w1 + v2.w * w2 + v3.w * w3;
    }
    for (; e < e1; e++) {
        int s = __ldg(col + e);
        float wt = __ldg(w + e);
        float4 v = load4(s);
        a.x += v.x * wt;
        a.y += v.y * wt;
        a.z += v.z * wt;
        a.w += v.w * wt;
    }
    float4 b4 = *(const float4*)(bias + lane * 4);
    a.x += b4.x; a.y += b4.y; a.z += b4.z; a.w += b4.w;

    // store agg as fp16 (one uint2 per lane)
    {
        __half2 lo = __floats2half2_rn(a.x, a.y);
        __half2 hi = __floats2half2_rn(a.z, a.w);
        uint2 u;
        u.x = *(uint32_t*)&lo;
        u.y = *(uint32_t*)&hi;
        *((uint2*)agg + (size_t)row * 32 + lane) = u;
    }

    // per-warp stats rows: plain STS, no contention
    int c = lane * 4;
    ssum[widx][c + 0] = a.x;
    ssum[widx][c + 1] = a.y;
    ssum[widx][c + 2] = a.z;
    ssum[widx][c + 3] = a.w;
    ssq[widx][c + 0] = a.x * a.x;
    ssq[widx][c + 1] = a.y * a.y;
    ssq[widx][c + 2] = a.z * a.z;
    ssq[widx][c + 3] = a.w * a.w;
    __syncthreads();

    // 8-way reduce: threads 0..127 -> sums, 128..255 -> squares
    if (tid < HID) {
        float s = 0.0f;
#pragma unroll
        for (int ww = 0; ww < 8; ww++) s += ssum[ww][tid];
        asm volatile("red.global.add.f32 [%0], %1;" ::"l"(stats + tid), "f"(s) : "memory");
    } else {
        int cc = tid - 128;
        float s = 0.0f;
#pragma unroll
        for (int ww = 0; ww < 8; ww++) s += ssq[ww][cc];
        asm volatile("red.global.add.f32 [%0], %1;" ::"l"(stats + HID + cc), "f"(s) : "memory");
    }
}

// ---------------- launch ----------------
extern "C" void kernel_launch(void* const* d_in, const int* in_sizes, int n_in,
                              void* d_out, int out_size) {
    const float* x = (const float*)d_in[0];
    const float* W_in = (const float*)d_in[1];
    const float* b_in = (const float*)d_in[2];
    const float* W_g = (const float*)d_in[3];
    const float* b_g = (const float*)d_in[4];
    const float* gamma = (const float*)d_in[5];
    const float* beta = (const float*)d_in[6];
    const float* W_out = (const float*)d_in[7];
    const float* b_out = (const float*)d_in[8];
    const void* ei = d_in[9];
    float* out = (float*)d_out;

    float *acc, *dis, *stats, *w;
    __half *t, *agg, *h0;
    uint32_t* wtf;
    int *cnt, *rowptr, *col, *blockoff;
    cudaGetSymbolAddress((void**)&t, g_t);
    cudaGetSymbolAddress((void**)&agg, g_agg);
    cudaGetSymbolAddress((void**)&h0, g_h0);
    cudaGetSymbolAddress((void**)&acc, g_acc);
    cudaGetSymbolAddress((void**)&dis, g_dis);
    cudaGetSymbolAddress((void**)&stats, g_stats);
    cudaGetSymbolAddress((void**)&wtf, g_wtf);
    cudaGetSymbolAddress((void**)&w, g_w);
    cudaGetSymbolAddress((void**)&cnt, g_cnt);
    cudaGetSymbolAddress((void**)&rowptr, g_rowptr);
    cudaGetSymbolAddress((void**)&col, g_col);
    cudaGetSymbolAddress((void**)&blockoff, g_blockoff);

    const int N = NNODES, E = NEDGES;

    // dyn smem: 2*AWORDS(1280) + Bs + scale/shift(256) words
    const int SH128 = (2 * 1280 + 8192 + 2 * HID) * 4;  // 44032
    const int SH64 = (2 * 1280 + 4096 + 2 * HID) * 4;   // 27648
    cudaFuncSetAttribute(gemm_tc<128, 0, 1, 1, 0>, cudaFuncAttributeMaxDynamicSharedMemorySize, SH128);
    cudaFuncSetAttribute(gemm_tc<128, 0, 0, 1, 1>, cudaFuncAttributeMaxDynamicSharedMemorySize, SH128);
    cudaFuncSetAttribute(gemm_tc<128, 1, 0, 1, 1>, cudaFuncAttributeMaxDynamicSharedMemorySize, SH128);
    cudaFuncSetAttribute(gemm_tc<128, 2, 0, 1, 1>, cudaFuncAttributeMaxDynamicSharedMemorySize, SH128);
    cudaFuncSetAttribute(gemm_tc<128, 3, 0, 1, 1>, cudaFuncAttributeMaxDynamicSharedMemorySize, SH128);
    cudaFuncSetAttribute(gemm_tc<64, 4, 1, 0, 1>, cudaFuncAttributeMaxDynamicSharedMemorySize, SH64);

    const int ntiles = (N + 63) / 64;  // 782
    const int gb = 444;                // persistent: 3 blocks/SM x 148 SMs
    const size_t WG = 8192;            // packed words per 128x128 matrix

    // GEMM0 kept at profiled launch index 3
    detect_zero_kernel<<<(N + 255) / 256, 256>>>((const long long*)ei, cnt, stats);   // 0
    wpack_kernel<<<(5 * 4096 + 2048 + 255) / 256, 256>>>(W_in, W_g, W_out, wtf);      // 1
    count_kernel<<<(E + 255) / 256, 256>>>(ei, cnt, E);                               // 2
    // 3 (PROFILED): h0 = x @ W_in + b_in  (fp16 out; doubles as skip)
    gemm_tc<128, 0, 1, 1, 0><<<gb, 256, SH128>>>(x, wtf, b_in, nullptr, nullptr, nullptr,
                                                 nullptr, nullptr, h0, N, ntiles);
    scan1_kernel<<<SCAN_NBLK, 256>>>(cnt, rowptr, blockoff, dis);                     // 4
    scan3_kernel<<<SCAN_NBLK, 256>>>(rowptr, blockoff, cnt);                          // 5
    scatter_kernel<<<(E + 255) / 256, 256>>>(ei, dis, rowptr, cnt, col, w, E);        // 6

    // t0 = h0 @ W_g[0]  (fp16 in, fp16 out)
    gemm_tc<128, 0, 0, 1, 1><<<gb, 256, SH128>>>(h0, wtf + WG, nullptr, nullptr, nullptr,
                                                 nullptr, nullptr, nullptr, t, N, ntiles);
    agg_stats_kernel<<<N / 8, 256>>>(t, dis, rowptr, col, w, b_g, agg, stats);
    // h1 = relu(norm0(agg0)); acc = h1; t1 = h1 @ W_g[1]
    gemm_tc<128, 1, 0, 1, 1><<<gb, 256, SH128>>>(agg, wtf + 2 * WG, nullptr, stats, gamma,
                                                 beta, nullptr, acc, t, N, ntiles);
    agg_stats_kernel<<<N / 8, 256>>>(t, dis, rowptr, col, w, b_g + HID, agg, stats + 256);
    // h2 = relu(norm1(agg1) + 0.5*h0); acc += h2; t2 = h2 @ W_g[2]
    gemm_tc<128, 2, 0, 1, 1><<<gb, 256, SH128>>>(agg, wtf + 3 * WG, nullptr, stats + 256,
                                                 gamma + HID, beta + HID, h0, acc, t, N, ntiles);
    agg_stats_kernel<<<N / 8, 256>>>(t, dis, rowptr, col, w, b_g + 2 * HID, agg, stats + 512);
    // h3 = relu(norm2(agg2)); acc += h3; t3 = h3 @ W_g[3]
    gemm_tc<128, 3, 0, 1, 1><<<gb, 256, SH128>>>(agg, wtf + 4 * WG, nullptr, stats + 512,
                                                 gamma + 2 * HID, beta + 2 * HID, nullptr, acc, t, N, ntiles);
    agg_stats_kernel<<<N / 8, 256>>>(t, dis, rowptr, col, w, b_g + 3 * HID, agg, stats + 768);
    // out = (acc + relu(norm3(agg3) + 0.5*h0)) @ W_out + b_out
    gemm_tc<64, 4, 1, 0, 1><<<gb, 256, SH64>>>(agg, wtf + 5 * WG, b_out, stats + 768,
                                               gamma + 3 * HID, beta + 3 * HID, h0, acc, out, N, ntiles);
}